// round 2
// baseline (speedup 1.0000x reference)
#include <cuda_runtime.h>
#include <cuda_bf16.h>
#include <math.h>

// Problem constants
#define B_    2
#define T_    2048
#define E_    2048
#define H_    32
#define G_    8
#define D_    64
#define QKV_F 3072   // (4+2)*8*64
#define QPK_  4      // Q_PER_KV

// ---------------- scratch (device globals; no allocation allowed) ----------
__device__ float g_qkv[(size_t)B_ * T_ * QKV_F];      // 50.3 MB
__device__ float g_q  [(size_t)B_ * H_ * T_ * D_];    // 33.5 MB (rope'd, pre-scaled)
__device__ float g_k  [(size_t)B_ * G_ * T_ * D_];    //  8.4 MB (rope'd)
__device__ float g_v  [(size_t)B_ * G_ * T_ * D_];    //  8.4 MB
__device__ float g_att[(size_t)B_ * T_ * E_];         // 33.5 MB

// ---------------------------------------------------------------------------
// SGEMM (NT): C[M,N] = A[M,K] * B[N,K]^T, all row-major, fp32.
// 128x128 block tile, BK=16, 256 threads, 8x8 microtile per thread.
// ---------------------------------------------------------------------------
__global__ __launch_bounds__(256, 2)
void sgemm_nt(const float* __restrict__ A, const float* __restrict__ Bm,
              float* __restrict__ C, int M, int N, int K) {
    __shared__ float As[16][132];   // k-major, padded
    __shared__ float Bs[16][132];

    const int t  = threadIdx.x;
    const int tx = t & 15;
    const int ty = t >> 4;
    const int bm = blockIdx.y * 128;
    const int bn = blockIdx.x * 128;

    const int lrow = t >> 2;          // 0..63
    const int lcol = (t & 3) << 2;    // 0,4,8,12

    const float* Ag = A  + (size_t)(bm + lrow) * K + lcol;
    const float* Bg = Bm + (size_t)(bn + lrow) * K + lcol;

    float acc[8][8];
#pragma unroll
    for (int i = 0; i < 8; i++)
#pragma unroll
        for (int j = 0; j < 8; j++) acc[i][j] = 0.0f;

    for (int k0 = 0; k0 < K; k0 += 16) {
#pragma unroll
        for (int rr = 0; rr < 2; rr++) {
            float4 a4 = *(const float4*)(Ag + k0 + (size_t)rr * 64 * K);
            int r = lrow + rr * 64;
            As[lcol + 0][r] = a4.x; As[lcol + 1][r] = a4.y;
            As[lcol + 2][r] = a4.z; As[lcol + 3][r] = a4.w;
            float4 b4 = *(const float4*)(Bg + k0 + (size_t)rr * 64 * K);
            Bs[lcol + 0][r] = b4.x; Bs[lcol + 1][r] = b4.y;
            Bs[lcol + 2][r] = b4.z; Bs[lcol + 3][r] = b4.w;
        }
        __syncthreads();

#pragma unroll
        for (int kk = 0; kk < 16; kk++) {
            float ra[8], rb[8];
            *(float4*)&ra[0] = *(const float4*)&As[kk][ty * 8];
            *(float4*)&ra[4] = *(const float4*)&As[kk][ty * 8 + 4];
            *(float4*)&rb[0] = *(const float4*)&Bs[kk][tx * 8];
            *(float4*)&rb[4] = *(const float4*)&Bs[kk][tx * 8 + 4];
#pragma unroll
            for (int i = 0; i < 8; i++)
#pragma unroll
                for (int j = 0; j < 8; j++)
                    acc[i][j] = fmaf(ra[i], rb[j], acc[i][j]);
        }
        __syncthreads();
    }

#pragma unroll
    for (int i = 0; i < 8; i++) {
        float* Crow = C + (size_t)(bm + ty * 8 + i) * N + bn + tx * 8;
        *(float4*)(Crow)     = make_float4(acc[i][0], acc[i][1], acc[i][2], acc[i][3]);
        *(float4*)(Crow + 4) = make_float4(acc[i][4], acc[i][5], acc[i][6], acc[i][7]);
    }
}

// ---------------------------------------------------------------------------
// RoPE + GQA split. One thread per qkv element.
// qkv layout: [(b*T+t)][g*384 + slot*64 + d], slot 0..3 = q, 4 = k, 5 = v.
// RoPE (full rotation, half=32):
//   d<32 : out = x[d]*cos[t][d]   - x[d+32]*sin[t][d]
//   d>=32: out = x[d]*cos[t][d-32]+ x[d-32]*sin[t][d-32]
// Q additionally pre-scaled by 1/sqrt(64) = 0.125.
// ---------------------------------------------------------------------------
__global__ void rope_split_kernel(const float* __restrict__ cosp,
                                  const float* __restrict__ sinp) {
    size_t idx = (size_t)blockIdx.x * blockDim.x + threadIdx.x;
    const size_t total = (size_t)B_ * T_ * QKV_F;
    if (idx >= total) return;

    const int d = (int)(idx & 63);
    const int f = (int)(idx % QKV_F);
    const size_t bt = idx / QKV_F;
    const int tpos = (int)(bt % T_);
    const int b = (int)(bt / T_);
    const int g = f / 384;
    const int slot = (f % 384) >> 6;

    float val = g_qkv[idx];
    if (slot <= 4) {  // q slots and k get RoPE
        const int dh = d & 31;
        const float c = cosp[tpos * 32 + dh];
        const float s = sinp[tpos * 32 + dh];
        // pair element: d <-> d^32 (d is the low 6 bits of idx, fields are 64-aligned)
        const float other = g_qkv[idx ^ 32];
        val = (d < 32) ? (val * c - other * s) : fmaf(val, c, other * s);
    }

    if (slot < QPK_) {
        const int h = g * QPK_ + slot;
        g_q[(((size_t)b * H_ + h) * T_ + tpos) * D_ + d] = val * 0.125f;
    } else if (slot == QPK_) {
        g_k[(((size_t)b * G_ + g) * T_ + tpos) * D_ + d] = val;
    } else {
        g_v[(((size_t)b * G_ + g) * T_ + tpos) * D_ + d] = val;
    }
}

// ---------------------------------------------------------------------------
// Flash attention (non-causal), fp32, online softmax.
// Block = (b, h, 64-row q tile). 256 threads as 16x16; thread (ty,tx) owns
// S rows 4ty..4ty+3 x S cols 4tx..4tx+3, and O rows 4ty.. x O dims 4tx..
// smem: qT/kT d-major [64][68] (float4-aligned, conflict-free reads),
//       vs row-major [64][64], ps [64][64].
// Staging: each of 256 threads loads 4 float4s -> full 64x64 tile (4096 floats).
// ---------------------------------------------------------------------------
#define AT_SMEM_FLOATS (64 * 68 * 2 + 64 * 64 * 2)

__global__ void flash_attn_kernel() {
    extern __shared__ float sm[];
    float* qT = sm;                  // [d][row], stride 68
    float* kT = sm + 64 * 68;        // [d][col], stride 68
    float* vs = sm + 2 * 64 * 68;    // [row][d], stride 64
    float* ps = vs + 64 * 64;        // [row][col], stride 64

    const int t  = threadIdx.x;
    const int tx = t & 15;
    const int ty = t >> 4;
    const int qt = blockIdx.x;
    const int h  = blockIdx.y;
    const int b  = blockIdx.z;
    const int g  = h >> 2;

    const int lr = t >> 2;           // 0..63 (loader row)
    const int lc = (t & 3) << 2;     // 0,4,8,12 (loader col group base)

    const float* Qg = g_q + (((size_t)b * H_ + h) * T_ + (size_t)qt * 64) * D_;
    const float* Kg = g_k + (((size_t)b * G_ + g) * T_) * D_;
    const float* Vg = g_v + (((size_t)b * G_ + g) * T_) * D_;

    {   // stage Q tile (transposed, d-major) — FULL 64 cols per row
#pragma unroll
        for (int cc = 0; cc < 4; cc++) {
            const int c = lc + 16 * cc;
            float4 q4 = *(const float4*)(Qg + (size_t)lr * D_ + c);
            qT[(c + 0) * 68 + lr] = q4.x; qT[(c + 1) * 68 + lr] = q4.y;
            qT[(c + 2) * 68 + lr] = q4.z; qT[(c + 3) * 68 + lr] = q4.w;
        }
    }

    float o[4][4];
    float m[4], l[4];
#pragma unroll
    for (int i = 0; i < 4; i++) {
        m[i] = -INFINITY; l[i] = 0.0f;
#pragma unroll
        for (int j = 0; j < 4; j++) o[i][j] = 0.0f;
    }

    for (int kt = 0; kt < T_ / 64; kt++) {
        {   // stage K (transposed) and V (row-major) tiles — FULL coverage
            const float* Kt = Kg + (size_t)kt * 64 * D_;
            const float* Vt = Vg + (size_t)kt * 64 * D_;
#pragma unroll
            for (int cc = 0; cc < 4; cc++) {
                const int c = lc + 16 * cc;
                float4 k4 = *(const float4*)(Kt + (size_t)lr * D_ + c);
                kT[(c + 0) * 68 + lr] = k4.x; kT[(c + 1) * 68 + lr] = k4.y;
                kT[(c + 2) * 68 + lr] = k4.z; kT[(c + 3) * 68 + lr] = k4.w;
                float4 v4 = *(const float4*)(Vt + (size_t)lr * D_ + c);
                *(float4*)&vs[lr * 64 + c] = v4;
            }
        }
        __syncthreads();

        // S = (q/8) k^T  (scale folded into q)
        float s[4][4];
#pragma unroll
        for (int i = 0; i < 4; i++)
#pragma unroll
            for (int j = 0; j < 4; j++) s[i][j] = 0.0f;

#pragma unroll 8
        for (int d = 0; d < 64; d++) {
            float4 qv = *(const float4*)&qT[d * 68 + 4 * ty];
            float4 kv = *(const float4*)&kT[d * 68 + 4 * tx];
            float qa[4] = {qv.x, qv.y, qv.z, qv.w};
            float ka[4] = {kv.x, kv.y, kv.z, kv.w};
#pragma unroll
            for (int i = 0; i < 4; i++)
#pragma unroll
                for (int j = 0; j < 4; j++)
                    s[i][j] = fmaf(qa[i], ka[j], s[i][j]);
        }

        // online softmax per row (row group = 16 lanes sharing ty)
#pragma unroll
        for (int i = 0; i < 4; i++) {
            float tmax = fmaxf(fmaxf(s[i][0], s[i][1]), fmaxf(s[i][2], s[i][3]));
#pragma unroll
            for (int off = 8; off > 0; off >>= 1)
                tmax = fmaxf(tmax, __shfl_xor_sync(0xffffffffu, tmax, off, 16));
            const float mn = fmaxf(m[i], tmax);
            const float corr = __expf(m[i] - mn);
            float rsum = 0.0f;
#pragma unroll
            for (int j = 0; j < 4; j++) {
                const float p = __expf(s[i][j] - mn);
                s[i][j] = p;
                rsum += p;
            }
#pragma unroll
            for (int off = 8; off > 0; off >>= 1)
                rsum += __shfl_xor_sync(0xffffffffu, rsum, off, 16);
            l[i] = l[i] * corr + rsum;
            m[i] = mn;
#pragma unroll
            for (int j = 0; j < 4; j++) o[i][j] *= corr;
            *(float4*)&ps[(4 * ty + i) * 64 + 4 * tx] =
                make_float4(s[i][0], s[i][1], s[i][2], s[i][3]);
        }
        __syncthreads();

        // O += P V
#pragma unroll 8
        for (int j = 0; j < 64; j++) {
            float4 vv = *(const float4*)&vs[j * 64 + 4 * tx];
#pragma unroll
            for (int i = 0; i < 4; i++) {
                const float p = ps[(4 * ty + i) * 64 + j];
                o[i][0] = fmaf(p, vv.x, o[i][0]);
                o[i][1] = fmaf(p, vv.y, o[i][1]);
                o[i][2] = fmaf(p, vv.z, o[i][2]);
                o[i][3] = fmaf(p, vv.w, o[i][3]);
            }
        }
        __syncthreads();
    }

    // normalize + write [b][t][h*64+d]
#pragma unroll
    for (int i = 0; i < 4; i++) {
        const float inv = 1.0f / l[i];
        const int trow = qt * 64 + 4 * ty + i;
        float* op = g_att + ((size_t)b * T_ + trow) * E_ + h * D_ + 4 * tx;
        *(float4*)op = make_float4(o[i][0] * inv, o[i][1] * inv,
                                   o[i][2] * inv, o[i][3] * inv);
    }
}

// ---------------------------------------------------------------------------
extern "C" void kernel_launch(void* const* d_in, const int* in_sizes, int n_in,
                              void* d_out, int out_size) {
    // Disambiguate inputs by element count (cos/sin share a size -> keep order).
    const float *x = 0, *cosp = 0, *sinp = 0, *attn_w = 0, *proj_w = 0;
    for (int i = 0; i < n_in; i++) {
        const float* p = (const float*)d_in[i];
        switch (in_sizes[i]) {
            case 8388608: x = p; break;                       // 2*2048*2048
            case 6291456: attn_w = p; break;                  // 3072*2048
            case 4194304: proj_w = p; break;                  // 2048*2048
            case 65536:   if (!cosp) cosp = p; else sinp = p; // 2048*32, order
                          break;
            default: break;
        }
    }
    float* out = (float*)d_out;                   // [B,T,E]

    float *qkv, *att;
    cudaGetSymbolAddress((void**)&qkv, g_qkv);
    cudaGetSymbolAddress((void**)&att, g_att);

    // 1) qkv = x @ attn_w^T   (M=4096, N=3072, K=2048)
    sgemm_nt<<<dim3(QKV_F / 128, (B_ * T_) / 128), 256>>>(
        x, attn_w, qkv, B_ * T_, QKV_F, E_);

    // 2) RoPE + GQA split (q pre-scaled by 1/sqrt(D))
    const size_t total = (size_t)B_ * T_ * QKV_F;
    rope_split_kernel<<<(unsigned)((total + 255) / 256), 256>>>(cosp, sinp);

    // 3) attention
    const int smem_bytes = AT_SMEM_FLOATS * (int)sizeof(float);
    cudaFuncSetAttribute((const void*)flash_attn_kernel,
                         cudaFuncAttributeMaxDynamicSharedMemorySize, smem_bytes);
    flash_attn_kernel<<<dim3(T_ / 64, H_, B_), 256, smem_bytes>>>();

    // 4) out = att @ proj_w^T   (M=4096, N=2048, K=2048)
    sgemm_nt<<<dim3(E_ / 128, (B_ * T_) / 128), 256>>>(
        att, proj_w, out, B_ * T_, E_, E_);
}

// round 3
// speedup vs baseline: 2.7311x; 2.7311x over previous
#include <cuda_runtime.h>
#include <cuda_bf16.h>
#include <math.h>

#define B_    2
#define T_    2048
#define E_    2048
#define H_    32
#define G_    8
#define D_    64
#define QKV_F 3072
#define QPK_  4

typedef __nv_bfloat16 bf16;
typedef unsigned int u32;

// ---------------- scratch (device globals; no allocation allowed) ----------
__device__ float g_qkv[(size_t)B_ * T_ * QKV_F];                       // fp32 qkv
__device__ bf16 g_xh [(size_t)B_ * T_ * E_],  g_xl [(size_t)B_ * T_ * E_];
__device__ bf16 g_awh[(size_t)QKV_F * E_],    g_awl[(size_t)QKV_F * E_];
__device__ bf16 g_pwh[(size_t)E_ * E_],       g_pwl[(size_t)E_ * E_];
__device__ bf16 g_qh [(size_t)B_ * H_ * T_ * D_], g_ql[(size_t)B_ * H_ * T_ * D_];
__device__ bf16 g_kh [(size_t)B_ * G_ * T_ * D_], g_kl[(size_t)B_ * G_ * T_ * D_];
__device__ bf16 g_vh [(size_t)B_ * G_ * T_ * D_], g_vl[(size_t)B_ * G_ * T_ * D_];
__device__ bf16 g_ath[(size_t)B_ * T_ * E_],  g_atl[(size_t)B_ * T_ * E_];

// ---------------- helpers --------------------------------------------------
// pack two fp32 -> bf16x2 (lo in low 16 bits)
__device__ __forceinline__ u32 packbf(float lo, float hi) {
    u32 r;
    asm("cvt.rn.bf16x2.f32 %0, %1, %2;" : "=r"(r) : "f"(hi), "f"(lo));
    return r;
}
__device__ __forceinline__ float bflo(u32 p) { return __uint_as_float(p << 16); }
__device__ __forceinline__ float bfhi(u32 p) { return __uint_as_float(p & 0xffff0000u); }

__device__ __forceinline__ void mma16816(float* c, u32 a0, u32 a1, u32 a2, u32 a3,
                                         u32 b0, u32 b1) {
    asm volatile(
        "mma.sync.aligned.m16n8k16.row.col.f32.bf16.bf16.f32 "
        "{%0,%1,%2,%3}, {%4,%5,%6,%7}, {%8,%9}, {%0,%1,%2,%3};"
        : "+f"(c[0]), "+f"(c[1]), "+f"(c[2]), "+f"(c[3])
        : "r"(a0), "r"(a1), "r"(a2), "r"(a3), "r"(b0), "r"(b1));
}

__device__ __forceinline__ void ldsm4t(u32* r, const bf16* p) {
    u32 a = (u32)__cvta_generic_to_shared(p);
    asm volatile("ldmatrix.sync.aligned.m8n8.x4.trans.shared.b16 {%0,%1,%2,%3}, [%4];"
                 : "=r"(r[0]), "=r"(r[1]), "=r"(r[2]), "=r"(r[3]) : "r"(a));
}

// ---------------- split fp32 -> (hi, lo) bf16 ------------------------------
__global__ void split_kernel(const float4* __restrict__ s, bf16* __restrict__ h,
                             bf16* __restrict__ l, int n4) {
    int i = blockIdx.x * blockDim.x + threadIdx.x;
    if (i >= n4) return;
    float4 v = s[i];
    u32 h0 = packbf(v.x, v.y);
    u32 l0 = packbf(v.x - bflo(h0), v.y - bfhi(h0));
    u32 h1 = packbf(v.z, v.w);
    u32 l1 = packbf(v.z - bflo(h1), v.w - bfhi(h1));
    ((u32*)h)[2 * i] = h0; ((u32*)h)[2 * i + 1] = h1;
    ((u32*)l)[2 * i] = l0; ((u32*)l)[2 * i + 1] = l1;
}

// ---------------- GEMM (NT): C[M,N] = (Ah+Al)(Bh+Bl)^T, split-3 bf16 -------
// 128x128 tile, BK=32, 256 threads = 8 warps (4M x 2N), warp tile 32x64.
#define GS  40   // smem row stride in halves
#define GSW 20   // ... in 32-bit words
__global__ __launch_bounds__(256, 2)
void gemm_bf16_split(const bf16* __restrict__ Ah, const bf16* __restrict__ Al,
                     const bf16* __restrict__ Bh, const bf16* __restrict__ Bl,
                     float* __restrict__ C, int M, int N, int K) {
    __shared__ bf16 sAh[128 * GS], sAl[128 * GS], sBh[128 * GS], sBl[128 * GS];
    u32* sAhW = (u32*)sAh; u32* sAlW = (u32*)sAl;
    u32* sBhW = (u32*)sBh; u32* sBlW = (u32*)sBl;

    const int t = threadIdx.x, lane = t & 31, w = t >> 5;
    const int g = lane >> 2, tq = lane & 3;
    const int wm = w & 3, wn = w >> 2;
    const int bm = blockIdx.y * 128, bn = blockIdx.x * 128;
    const int lrow = t >> 2, lc8 = (t & 3) * 8;

    float acc[2][8][4];
#pragma unroll
    for (int mt = 0; mt < 2; mt++)
#pragma unroll
        for (int nt = 0; nt < 8; nt++)
#pragma unroll
            for (int i = 0; i < 4; i++) acc[mt][nt][i] = 0.0f;

    for (int k0 = 0; k0 < K; k0 += 32) {
#pragma unroll
        for (int rr = 0; rr < 2; rr++) {
            const int row = lrow + rr * 64;
            const size_t goA = (size_t)(bm + row) * K + k0 + lc8;
            const size_t goB = (size_t)(bn + row) * K + k0 + lc8;
            *(uint4*)&sAh[row * GS + lc8] = *(const uint4*)&Ah[goA];
            *(uint4*)&sAl[row * GS + lc8] = *(const uint4*)&Al[goA];
            *(uint4*)&sBh[row * GS + lc8] = *(const uint4*)&Bh[goB];
            *(uint4*)&sBl[row * GS + lc8] = *(const uint4*)&Bl[goB];
        }
        __syncthreads();

#pragma unroll
        for (int c = 0; c < 2; c++) {
            u32 ah[2][4], al[2][4];
#pragma unroll
            for (int mt = 0; mt < 2; mt++) {
                const int ro = (wm * 32 + mt * 16 + g) * GSW + tq + c * 8;
                ah[mt][0] = sAhW[ro];               ah[mt][1] = sAhW[ro + 8 * GSW];
                ah[mt][2] = sAhW[ro + 4];           ah[mt][3] = sAhW[ro + 8 * GSW + 4];
                al[mt][0] = sAlW[ro];               al[mt][1] = sAlW[ro + 8 * GSW];
                al[mt][2] = sAlW[ro + 4];           al[mt][3] = sAlW[ro + 8 * GSW + 4];
            }
#pragma unroll
            for (int nt = 0; nt < 8; nt++) {
                const int ko = (wn * 64 + nt * 8 + g) * GSW + tq + c * 8;
                const u32 bh0 = sBhW[ko], bh1 = sBhW[ko + 4];
                const u32 bl0 = sBlW[ko], bl1 = sBlW[ko + 4];
#pragma unroll
                for (int mt = 0; mt < 2; mt++) {
                    mma16816(acc[mt][nt], ah[mt][0], ah[mt][1], ah[mt][2], ah[mt][3], bh0, bh1);
                    mma16816(acc[mt][nt], ah[mt][0], ah[mt][1], ah[mt][2], ah[mt][3], bl0, bl1);
                    mma16816(acc[mt][nt], al[mt][0], al[mt][1], al[mt][2], al[mt][3], bh0, bh1);
                }
            }
        }
        __syncthreads();
    }

#pragma unroll
    for (int mt = 0; mt < 2; mt++) {
        const int r0 = bm + wm * 32 + mt * 16 + g;
#pragma unroll
        for (int nt = 0; nt < 8; nt++) {
            const int cc = bn + wn * 64 + nt * 8 + 2 * tq;
            *(float2*)&C[(size_t)r0 * N + cc]       = make_float2(acc[mt][nt][0], acc[mt][nt][1]);
            *(float2*)&C[(size_t)(r0 + 8) * N + cc] = make_float2(acc[mt][nt][2], acc[mt][nt][3]);
        }
    }
}

// ---------------- RoPE + GQA split -> bf16 hi/lo ---------------------------
__global__ void rope_split_kernel(const float* __restrict__ cosp,
                                  const float* __restrict__ sinp) {
    size_t idx = (size_t)blockIdx.x * blockDim.x + threadIdx.x;
    const size_t total = (size_t)B_ * T_ * QKV_F;
    if (idx >= total) return;

    const int d = (int)(idx & 63);
    const int f = (int)(idx % QKV_F);
    const size_t bt = idx / QKV_F;
    const int tpos = (int)(bt % T_);
    const int b = (int)(bt / T_);
    const int g = f / 384;
    const int slot = (f % 384) >> 6;

    float val = g_qkv[idx];
    if (slot <= 4) {
        const int dh = d & 31;
        const float c = cosp[tpos * 32 + dh];
        const float s = sinp[tpos * 32 + dh];
        const float other = g_qkv[idx ^ 32];
        val = (d < 32) ? (val * c - other * s) : fmaf(val, c, other * s);
    }

    if (slot < QPK_) {
        val *= 0.125f;  // fold 1/sqrt(D)
        const int h = g * QPK_ + slot;
        const size_t o = (((size_t)b * H_ + h) * T_ + tpos) * D_ + d;
        bf16 hb = __float2bfloat16_rn(val);
        g_qh[o] = hb;
        g_ql[o] = __float2bfloat16_rn(val - __bfloat162float(hb));
    } else {
        const size_t o = (((size_t)b * G_ + g) * T_ + tpos) * D_ + d;
        bf16 hb = __float2bfloat16_rn(val);
        bf16 lb = __float2bfloat16_rn(val - __bfloat162float(hb));
        if (slot == QPK_) { g_kh[o] = hb; g_kl[o] = lb; }
        else              { g_vh[o] = hb; g_vl[o] = lb; }
    }
}

// ---------------- flash attention with HMMA split-3 ------------------------
// Block: (b, h, 128 q-rows). 256 threads = 8 warps, warp = 16 q-rows.
// kv tiles of 64. smem strides 72 halves (conflict-free frag loads).
#define AS  72
#define ASW 36
#define AT_SMEM_BYTES ((128 * AS * 2 + 64 * AS * 4) * 2)

__global__ __launch_bounds__(256, 2) void attn_mma_kernel() {
    extern __shared__ bf16 sm[];
    bf16* Qh = sm;
    bf16* Ql = sm + 128 * AS;
    bf16* Kh = sm + 2 * 128 * AS;
    bf16* Kl = Kh + 64 * AS;
    bf16* Vh = Kl + 64 * AS;
    bf16* Vl = Vh + 64 * AS;
    u32* QhW = (u32*)Qh; u32* QlW = (u32*)Ql;
    u32* KhW = (u32*)Kh; u32* KlW = (u32*)Kl;

    const int t = threadIdx.x, lane = t & 31, w = t >> 5;
    const int g = lane >> 2, tq = lane & 3;
    const int qt = blockIdx.x, h = blockIdx.y, b = blockIdx.z, grp = h >> 2;

    {   // stage Q (128 x 64, hi+lo)
        const bf16* Qgh = g_qh + (((size_t)b * H_ + h) * T_ + (size_t)qt * 128) * D_;
        const bf16* Qgl = g_ql + (((size_t)b * H_ + h) * T_ + (size_t)qt * 128) * D_;
#pragma unroll
        for (int i = 0; i < 4; i++) {
            const int e = t + i * 256, row = e >> 3, c8 = (e & 7) * 8;
            *(uint4*)&Qh[row * AS + c8] = *(const uint4*)&Qgh[row * D_ + c8];
            *(uint4*)&Ql[row * AS + c8] = *(const uint4*)&Qgl[row * D_ + c8];
        }
    }

    float oacc[8][4];
#pragma unroll
    for (int dt = 0; dt < 8; dt++)
#pragma unroll
        for (int i = 0; i < 4; i++) oacc[dt][i] = 0.0f;
    float mrow[2] = {-1e30f, -1e30f};
    float lrow[2] = {0.0f, 0.0f};

    const size_t kvbase = ((size_t)b * G_ + grp) * T_ * D_;

    for (int kt = 0; kt < T_ / 64; kt++) {
        {   // stage K, V tiles (64 x 64, hi+lo each)
            const size_t kb = kvbase + (size_t)kt * 64 * D_;
#pragma unroll
            for (int i = 0; i < 2; i++) {
                const int e = t + i * 256, row = e >> 3, c8 = (e & 7) * 8;
                const size_t go = kb + (size_t)row * D_ + c8;
                *(uint4*)&Kh[row * AS + c8] = *(const uint4*)&g_kh[go];
                *(uint4*)&Kl[row * AS + c8] = *(const uint4*)&g_kl[go];
                *(uint4*)&Vh[row * AS + c8] = *(const uint4*)&g_vh[go];
                *(uint4*)&Vl[row * AS + c8] = *(const uint4*)&g_vl[go];
            }
        }
        __syncthreads();

        // ---- S = Q K^T (split-3) ----
        float sacc[8][4];
#pragma unroll
        for (int nt = 0; nt < 8; nt++)
#pragma unroll
            for (int i = 0; i < 4; i++) sacc[nt][i] = 0.0f;

        const int qw = (w * 16 + g) * ASW + tq;
#pragma unroll
        for (int c = 0; c < 4; c++) {
            const int qo = qw + c * 8;
            const u32 ah0 = QhW[qo],     ah1 = QhW[qo + 8 * ASW];
            const u32 ah2 = QhW[qo + 4], ah3 = QhW[qo + 8 * ASW + 4];
            const u32 al0 = QlW[qo],     al1 = QlW[qo + 8 * ASW];
            const u32 al2 = QlW[qo + 4], al3 = QlW[qo + 8 * ASW + 4];
#pragma unroll
            for (int nt = 0; nt < 8; nt++) {
                const int ko = (nt * 8 + g) * ASW + tq + c * 8;
                const u32 bh0 = KhW[ko], bh1 = KhW[ko + 4];
                const u32 bl0 = KlW[ko], bl1 = KlW[ko + 4];
                mma16816(sacc[nt], ah0, ah1, ah2, ah3, bh0, bh1);
                mma16816(sacc[nt], ah0, ah1, ah2, ah3, bl0, bl1);
                mma16816(sacc[nt], al0, al1, al2, al3, bh0, bh1);
            }
        }

        // ---- online softmax (rows g and g+8 per thread) ----
#pragma unroll
        for (int r = 0; r < 2; r++) {
            float rmax = -1e30f;
#pragma unroll
            for (int nt = 0; nt < 8; nt++)
                rmax = fmaxf(rmax, fmaxf(sacc[nt][2 * r], sacc[nt][2 * r + 1]));
            rmax = fmaxf(rmax, __shfl_xor_sync(0xffffffffu, rmax, 1));
            rmax = fmaxf(rmax, __shfl_xor_sync(0xffffffffu, rmax, 2));
            const float mn = fmaxf(mrow[r], rmax);
            const float corr = __expf(mrow[r] - mn);
            mrow[r] = mn;
            float rs = 0.0f;
#pragma unroll
            for (int nt = 0; nt < 8; nt++) {
                const float p0 = __expf(sacc[nt][2 * r] - mn);
                const float p1 = __expf(sacc[nt][2 * r + 1] - mn);
                sacc[nt][2 * r] = p0; sacc[nt][2 * r + 1] = p1;
                rs += p0 + p1;
            }
            rs += __shfl_xor_sync(0xffffffffu, rs, 1);
            rs += __shfl_xor_sync(0xffffffffu, rs, 2);
            lrow[r] = lrow[r] * corr + rs;
#pragma unroll
            for (int dt = 0; dt < 8; dt++) {
                oacc[dt][2 * r] *= corr; oacc[dt][2 * r + 1] *= corr;
            }
        }

        // ---- O += P V (split-3; P from S-frags, V via ldmatrix.trans) ----
        const int vrow = lane & 15;
        const int vcol = (lane >> 4) << 3;
#pragma unroll
        for (int c = 0; c < 4; c++) {
            u32 ph[4], pl[4];
            {
                float p0 = sacc[2 * c][0], p1 = sacc[2 * c][1];
                ph[0] = packbf(p0, p1);
                pl[0] = packbf(p0 - bflo(ph[0]), p1 - bfhi(ph[0]));
                p0 = sacc[2 * c][2]; p1 = sacc[2 * c][3];
                ph[1] = packbf(p0, p1);
                pl[1] = packbf(p0 - bflo(ph[1]), p1 - bfhi(ph[1]));
                p0 = sacc[2 * c + 1][0]; p1 = sacc[2 * c + 1][1];
                ph[2] = packbf(p0, p1);
                pl[2] = packbf(p0 - bflo(ph[2]), p1 - bfhi(ph[2]));
                p0 = sacc[2 * c + 1][2]; p1 = sacc[2 * c + 1][3];
                ph[3] = packbf(p0, p1);
                pl[3] = packbf(p0 - bflo(ph[3]), p1 - bfhi(ph[3]));
            }
#pragma unroll
            for (int d2 = 0; d2 < 4; d2++) {
                u32 vh[4], vl[4];
                const int so = (c * 16 + vrow) * AS + d2 * 16 + vcol;
                ldsm4t(vh, &Vh[so]);
                ldsm4t(vl, &Vl[so]);
                mma16816(oacc[2 * d2],     ph[0], ph[1], ph[2], ph[3], vh[0], vh[1]);
                mma16816(oacc[2 * d2],     ph[0], ph[1], ph[2], ph[3], vl[0], vl[1]);
                mma16816(oacc[2 * d2],     pl[0], pl[1], pl[2], pl[3], vh[0], vh[1]);
                mma16816(oacc[2 * d2 + 1], ph[0], ph[1], ph[2], ph[3], vh[2], vh[3]);
                mma16816(oacc[2 * d2 + 1], ph[0], ph[1], ph[2], ph[3], vl[2], vl[3]);
                mma16816(oacc[2 * d2 + 1], pl[0], pl[1], pl[2], pl[3], vh[2], vh[3]);
            }
        }
        __syncthreads();
    }

    // ---- normalize + write bf16 hi/lo into att (GEMM2 A operand) ----
    const float inv0 = 1.0f / lrow[0];
    const float inv1 = 1.0f / lrow[1];
    const size_t row0 = (size_t)b * T_ + (size_t)qt * 128 + w * 16 + g;
    const size_t row1 = row0 + 8;
#pragma unroll
    for (int dt = 0; dt < 8; dt++) {
        const int col = h * D_ + dt * 8 + 2 * tq;
        const float a0 = oacc[dt][0] * inv0, a1 = oacc[dt][1] * inv0;
        const float b0 = oacc[dt][2] * inv1, b1 = oacc[dt][3] * inv1;
        const u32 h0 = packbf(a0, a1);
        const u32 l0 = packbf(a0 - bflo(h0), a1 - bfhi(h0));
        const u32 h1 = packbf(b0, b1);
        const u32 l1 = packbf(b0 - bflo(h1), b1 - bfhi(h1));
        *(u32*)&g_ath[row0 * E_ + col] = h0;
        *(u32*)&g_atl[row0 * E_ + col] = l0;
        *(u32*)&g_ath[row1 * E_ + col] = h1;
        *(u32*)&g_atl[row1 * E_ + col] = l1;
    }
}

// ---------------------------------------------------------------------------
extern "C" void kernel_launch(void* const* d_in, const int* in_sizes, int n_in,
                              void* d_out, int out_size) {
    const float *x = 0, *cosp = 0, *sinp = 0, *attn_w = 0, *proj_w = 0;
    for (int i = 0; i < n_in; i++) {
        const float* p = (const float*)d_in[i];
        switch (in_sizes[i]) {
            case 8388608: x = p; break;
            case 6291456: attn_w = p; break;
            case 4194304: proj_w = p; break;
            case 65536:   if (!cosp) cosp = p; else sinp = p; break;
            default: break;
        }
    }
    float* out = (float*)d_out;

    float* qkv;
    bf16 *xh, *xl, *awh, *awl, *pwh, *pwl, *ath, *atl;
    cudaGetSymbolAddress((void**)&qkv, g_qkv);
    cudaGetSymbolAddress((void**)&xh,  g_xh);  cudaGetSymbolAddress((void**)&xl,  g_xl);
    cudaGetSymbolAddress((void**)&awh, g_awh); cudaGetSymbolAddress((void**)&awl, g_awl);
    cudaGetSymbolAddress((void**)&pwh, g_pwh); cudaGetSymbolAddress((void**)&pwl, g_pwl);
    cudaGetSymbolAddress((void**)&ath, g_ath); cudaGetSymbolAddress((void**)&atl, g_atl);

    // 0) split fp32 inputs into bf16 hi/lo pairs
    split_kernel<<<(8388608 / 4 + 255) / 256, 256>>>((const float4*)x, xh, xl, 8388608 / 4);
    split_kernel<<<(6291456 / 4 + 255) / 256, 256>>>((const float4*)attn_w, awh, awl, 6291456 / 4);
    split_kernel<<<(4194304 / 4 + 255) / 256, 256>>>((const float4*)proj_w, pwh, pwl, 4194304 / 4);

    // 1) qkv = x @ attn_w^T  (fp32 out)
    gemm_bf16_split<<<dim3(QKV_F / 128, (B_ * T_) / 128), 256>>>(
        xh, xl, awh, awl, qkv, B_ * T_, QKV_F, E_);

    // 2) RoPE + GQA split -> bf16 hi/lo q/k/v
    const size_t total = (size_t)B_ * T_ * QKV_F;
    rope_split_kernel<<<(unsigned)((total + 255) / 256), 256>>>(cosp, sinp);

    // 3) attention (writes bf16 hi/lo att directly)
    cudaFuncSetAttribute((const void*)attn_mma_kernel,
                         cudaFuncAttributeMaxDynamicSharedMemorySize, AT_SMEM_BYTES);
    attn_mma_kernel<<<dim3(T_ / 128, H_, B_), 256, AT_SMEM_BYTES>>>();

    // 4) out = att @ proj_w^T
    gemm_bf16_split<<<dim3(E_ / 128, (B_ * T_) / 128), 256>>>(
        ath, atl, pwh, pwl, out, B_ * T_, E_, E_);
}

// round 5
// speedup vs baseline: 2.7720x; 1.0150x over previous
#include <cuda_runtime.h>
#include <cuda_bf16.h>
#include <math.h>

#define B_    2
#define T_    2048
#define E_    2048
#define H_    32
#define G_    8
#define D_    64
#define QKV_F 3072
#define QPK_  4

typedef __nv_bfloat16 bf16;
typedef unsigned int u32;

// ---------------- scratch (device globals; no allocation allowed) ----------
__device__ float g_qkv[(size_t)B_ * T_ * QKV_F];
__device__ bf16 g_xh [(size_t)B_ * T_ * E_],  g_xl [(size_t)B_ * T_ * E_];
__device__ bf16 g_awh[(size_t)QKV_F * E_],    g_awl[(size_t)QKV_F * E_];
__device__ bf16 g_pwh[(size_t)E_ * E_],       g_pwl[(size_t)E_ * E_];
__device__ bf16 g_qh [(size_t)B_ * H_ * T_ * D_], g_ql[(size_t)B_ * H_ * T_ * D_];
__device__ bf16 g_kh [(size_t)B_ * G_ * T_ * D_], g_kl[(size_t)B_ * G_ * T_ * D_];
__device__ bf16 g_vh [(size_t)B_ * G_ * T_ * D_], g_vl[(size_t)B_ * G_ * T_ * D_];
__device__ bf16 g_ath[(size_t)B_ * T_ * E_],  g_atl[(size_t)B_ * T_ * E_];

// ---------------- helpers --------------------------------------------------
__device__ __forceinline__ u32 packbf(float lo, float hi) {
    u32 r;
    asm("cvt.rn.bf16x2.f32 %0, %1, %2;" : "=r"(r) : "f"(hi), "f"(lo));
    return r;
}
__device__ __forceinline__ float bflo(u32 p) { return __uint_as_float(p << 16); }
__device__ __forceinline__ float bfhi(u32 p) { return __uint_as_float(p & 0xffff0000u); }

__device__ __forceinline__ void mma16816(float* c, u32 a0, u32 a1, u32 a2, u32 a3,
                                         u32 b0, u32 b1) {
    asm volatile(
        "mma.sync.aligned.m16n8k16.row.col.f32.bf16.bf16.f32 "
        "{%0,%1,%2,%3}, {%4,%5,%6,%7}, {%8,%9}, {%0,%1,%2,%3};"
        : "+f"(c[0]), "+f"(c[1]), "+f"(c[2]), "+f"(c[3])
        : "r"(a0), "r"(a1), "r"(a2), "r"(a3), "r"(b0), "r"(b1));
}

__device__ __forceinline__ void ldsm4t(u32* r, const bf16* p) {
    u32 a = (u32)__cvta_generic_to_shared(p);
    asm volatile("ldmatrix.sync.aligned.m8n8.x4.trans.shared.b16 {%0,%1,%2,%3}, [%4];"
                 : "=r"(r[0]), "=r"(r[1]), "=r"(r[2]), "=r"(r[3]) : "r"(a));
}

__device__ __forceinline__ u32 smem_u32(const void* p) {
    return (u32)__cvta_generic_to_shared(p);
}
__device__ __forceinline__ void cpasync16(u32 dst, const void* src) {
    asm volatile("cp.async.cg.shared.global [%0], [%1], 16;" :: "r"(dst), "l"(src));
}
__device__ __forceinline__ void cpcommit() { asm volatile("cp.async.commit_group;" ::: "memory"); }
__device__ __forceinline__ void cpwait0()  { asm volatile("cp.async.wait_group 0;" ::: "memory"); }
__device__ __forceinline__ void cpwait1()  { asm volatile("cp.async.wait_group 1;" ::: "memory"); }

// ---------------- split fp32 -> (hi, lo) bf16 ------------------------------
__global__ void split_kernel(const float4* __restrict__ s, bf16* __restrict__ h,
                             bf16* __restrict__ l, int n4) {
    int i = blockIdx.x * blockDim.x + threadIdx.x;
    if (i >= n4) return;
    float4 v = s[i];
    u32 h0 = packbf(v.x, v.y);
    u32 l0 = packbf(v.x - bflo(h0), v.y - bfhi(h0));
    u32 h1 = packbf(v.z, v.w);
    u32 l1 = packbf(v.z - bflo(h1), v.w - bfhi(h1));
    ((u32*)h)[2 * i] = h0; ((u32*)h)[2 * i + 1] = h1;
    ((u32*)l)[2 * i] = l0; ((u32*)l)[2 * i + 1] = l1;
}

// ===========================================================================
// GEMM (NT): C = (Ah+Al)(Bh+Bl)^T, split-3 bf16 HMMA, cp.async 2-stage.
// 128x128 tile, BK=32, 256 threads = 8 warps (4M x 2N).
// Stage layout (bytes): Ah @0, Al @10240, Bh @20480, Bl @30720 ; row stride 80B.
// ===========================================================================
#define GSW 20                  // smem row stride in 32-bit words
#define GST 40960               // bytes per stage
#define GEMM_SMEM (2 * GST)

__global__ __launch_bounds__(256, 2)
void gemm_bf16_split(const bf16* __restrict__ Ah, const bf16* __restrict__ Al,
                     const bf16* __restrict__ Bh, const bf16* __restrict__ Bl,
                     float* __restrict__ C, int M, int N, int K) {
    extern __shared__ char smc[];
    const u32 sb = smem_u32(smc);

    const int t = threadIdx.x, lane = t & 31, w = t >> 5;
    const int g = lane >> 2, tq = lane & 3;
    const int wm = w & 3, wn = w >> 2;
    const int bm = blockIdx.y * 128, bn = blockIdx.x * 128;

    float acc[2][8][4];
#pragma unroll
    for (int mt = 0; mt < 2; mt++)
#pragma unroll
        for (int nt = 0; nt < 8; nt++)
#pragma unroll
            for (int i = 0; i < 4; i++) acc[mt][nt][i] = 0.0f;

    const int NS = K / 32;

    // prologue: stage 0
    {
#pragma unroll
        for (int i = 0; i < 2; i++) {
            const int id = t + i * 256, row = id >> 2, cq = id & 3;
            const u32 d = sb + (u32)(row * 80 + cq * 16);
            const size_t ga = (size_t)(bm + row) * K + cq * 8;
            const size_t gb = (size_t)(bn + row) * K + cq * 8;
            cpasync16(d,         Ah + ga); cpasync16(d + 10240, Al + ga);
            cpasync16(d + 20480, Bh + gb); cpasync16(d + 30720, Bl + gb);
        }
        cpcommit();
    }

    for (int s = 0; s < NS; s++) {
        if (s + 1 < NS) {   // prefetch next stage into other buffer
            const u32 base = sb + (u32)((s + 1) & 1) * GST;
            const int k0 = (s + 1) * 32;
#pragma unroll
            for (int i = 0; i < 2; i++) {
                const int id = t + i * 256, row = id >> 2, cq = id & 3;
                const u32 d = base + (u32)(row * 80 + cq * 16);
                const size_t ga = (size_t)(bm + row) * K + k0 + cq * 8;
                const size_t gb = (size_t)(bn + row) * K + k0 + cq * 8;
                cpasync16(d,         Ah + ga); cpasync16(d + 10240, Al + ga);
                cpasync16(d + 20480, Bh + gb); cpasync16(d + 30720, Bl + gb);
            }
            cpcommit();
            cpwait1();
        } else {
            cpwait0();
        }
        __syncthreads();

        const char* base = smc + (size_t)(s & 1) * GST;
        const u32* sAhW = (const u32*)(base);
        const u32* sAlW = (const u32*)(base + 10240);
        const u32* sBhW = (const u32*)(base + 20480);
        const u32* sBlW = (const u32*)(base + 30720);

#pragma unroll
        for (int c = 0; c < 2; c++) {
            u32 ah[2][4], al[2][4];
#pragma unroll
            for (int mt = 0; mt < 2; mt++) {
                const int ro = (wm * 32 + mt * 16 + g) * GSW + tq + c * 8;
                ah[mt][0] = sAhW[ro];               ah[mt][1] = sAhW[ro + 8 * GSW];
                ah[mt][2] = sAhW[ro + 4];           ah[mt][3] = sAhW[ro + 8 * GSW + 4];
                al[mt][0] = sAlW[ro];               al[mt][1] = sAlW[ro + 8 * GSW];
                al[mt][2] = sAlW[ro + 4];           al[mt][3] = sAlW[ro + 8 * GSW + 4];
            }
#pragma unroll
            for (int nt = 0; nt < 8; nt++) {
                const int ko = (wn * 64 + nt * 8 + g) * GSW + tq + c * 8;
                const u32 bh0 = sBhW[ko], bh1 = sBhW[ko + 4];
                const u32 bl0 = sBlW[ko], bl1 = sBlW[ko + 4];
#pragma unroll
                for (int mt = 0; mt < 2; mt++) {
                    mma16816(acc[mt][nt], ah[mt][0], ah[mt][1], ah[mt][2], ah[mt][3], bh0, bh1);
                    mma16816(acc[mt][nt], ah[mt][0], ah[mt][1], ah[mt][2], ah[mt][3], bl0, bl1);
                    mma16816(acc[mt][nt], al[mt][0], al[mt][1], al[mt][2], al[mt][3], bh0, bh1);
                }
            }
        }
        __syncthreads();
    }

#pragma unroll
    for (int mt = 0; mt < 2; mt++) {
        const int r0 = bm + wm * 32 + mt * 16 + g;
#pragma unroll
        for (int nt = 0; nt < 8; nt++) {
            const int cc = bn + wn * 64 + nt * 8 + 2 * tq;
            *(float2*)&C[(size_t)r0 * N + cc]       = make_float2(acc[mt][nt][0], acc[mt][nt][1]);
            *(float2*)&C[(size_t)(r0 + 8) * N + cc] = make_float2(acc[mt][nt][2], acc[mt][nt][3]);
        }
    }
}

// ---------------- RoPE + GQA split -> bf16 hi/lo ---------------------------
__global__ void rope_split_kernel(const float* __restrict__ cosp,
                                  const float* __restrict__ sinp) {
    size_t idx = (size_t)blockIdx.x * blockDim.x + threadIdx.x;
    const size_t total = (size_t)B_ * T_ * QKV_F;
    if (idx >= total) return;

    const int d = (int)(idx & 63);
    const int f = (int)(idx % QKV_F);
    const size_t bt = idx / QKV_F;
    const int tpos = (int)(bt % T_);
    const int b = (int)(bt / T_);
    const int g = f / 384;
    const int slot = (f % 384) >> 6;

    float val = g_qkv[idx];
    if (slot <= 4) {
        const int dh = d & 31;
        const float c = cosp[tpos * 32 + dh];
        const float s = sinp[tpos * 32 + dh];
        const float other = g_qkv[idx ^ 32];
        val = (d < 32) ? (val * c - other * s) : fmaf(val, c, other * s);
    }

    if (slot < QPK_) {
        val *= 0.125f;
        const int h = g * QPK_ + slot;
        const size_t o = (((size_t)b * H_ + h) * T_ + tpos) * D_ + d;
        bf16 hb = __float2bfloat16_rn(val);
        g_qh[o] = hb;
        g_ql[o] = __float2bfloat16_rn(val - __bfloat162float(hb));
    } else {
        const size_t o = (((size_t)b * G_ + g) * T_ + tpos) * D_ + d;
        bf16 hb = __float2bfloat16_rn(val);
        bf16 lb = __float2bfloat16_rn(val - __bfloat162float(hb));
        if (slot == QPK_) { g_kh[o] = hb; g_kl[o] = lb; }
        else              { g_vh[o] = hb; g_vl[o] = lb; }
    }
}

// ===========================================================================
// Flash attention, HMMA split-3, cp.async double-buffered K/V.
// Block (b, h, 128 q rows), 256 threads = 8 warps (16 q-rows each), kv tile 64.
// Dynamic smem: Qh @0, Ql @18432; stage st @36864+st*36864:
//   Kh +0, Kl +9216, Vh +18432, Vl +27648.  Row stride 144B (72 halves).
// ===========================================================================
#define AS  72
#define ASW 36
#define AQB   18432
#define AKVST 36864
#define AT_SMEM_BYTES (2 * AQB + 2 * AKVST)

__global__ __launch_bounds__(256, 2) void attn_mma_kernel() {
    extern __shared__ char smc[];
    const u32 sb = smem_u32(smc);
    bf16* Qh = (bf16*)smc;
    bf16* Ql = (bf16*)(smc + AQB);
    u32* QhW = (u32*)Qh; u32* QlW = (u32*)Ql;

    const int t = threadIdx.x, lane = t & 31, w = t >> 5;
    const int g = lane >> 2, tq = lane & 3;
    const int qt = blockIdx.x, h = blockIdx.y, b = blockIdx.z, grp = h >> 2;

    {   // stage Q (128 x 64, hi+lo), regular stores
        const bf16* Qgh = g_qh + (((size_t)b * H_ + h) * T_ + (size_t)qt * 128) * D_;
        const bf16* Qgl = g_ql + (((size_t)b * H_ + h) * T_ + (size_t)qt * 128) * D_;
#pragma unroll
        for (int i = 0; i < 4; i++) {
            const int e = t + i * 256, row = e >> 3, c8 = (e & 7) * 8;
            *(uint4*)&Qh[row * AS + c8] = *(const uint4*)&Qgh[row * D_ + c8];
            *(uint4*)&Ql[row * AS + c8] = *(const uint4*)&Qgl[row * D_ + c8];
        }
    }

    float oacc[8][4];
#pragma unroll
    for (int dt = 0; dt < 8; dt++)
#pragma unroll
        for (int i = 0; i < 4; i++) oacc[dt][i] = 0.0f;
    float mrow[2] = {-1e30f, -1e30f};
    float lrow[2] = {0.0f, 0.0f};

    const size_t kvbase = ((size_t)b * G_ + grp) * T_ * D_;
    const int NKT = T_ / 64;

    {   // prologue: stage kt=0 into buffer 0
        const size_t kb = kvbase;
        const u32 base = sb + 2 * AQB;
#pragma unroll
        for (int i = 0; i < 2; i++) {
            const int id = t + i * 256, row = id >> 3, cq = id & 7;
            const u32 d = base + (u32)(row * 144 + cq * 16);
            const size_t go = kb + (size_t)row * 64 + cq * 8;
            cpasync16(d,         g_kh + go); cpasync16(d + 9216,  g_kl + go);
            cpasync16(d + 18432, g_vh + go); cpasync16(d + 27648, g_vl + go);
        }
        cpcommit();
    }

    for (int kt = 0; kt < NKT; kt++) {
        if (kt + 1 < NKT) {   // prefetch next K/V tile
            const size_t kb = kvbase + (size_t)(kt + 1) * 64 * D_;
            const u32 base = sb + 2 * AQB + (u32)((kt + 1) & 1) * AKVST;
#pragma unroll
            for (int i = 0; i < 2; i++) {
                const int id = t + i * 256, row = id >> 3, cq = id & 7;
                const u32 d = base + (u32)(row * 144 + cq * 16);
                const size_t go = kb + (size_t)row * 64 + cq * 8;
                cpasync16(d,         g_kh + go); cpasync16(d + 9216,  g_kl + go);
                cpasync16(d + 18432, g_vh + go); cpasync16(d + 27648, g_vl + go);
            }
            cpcommit();
            cpwait1();
        } else {
            cpwait0();
        }
        __syncthreads();

        const char* stb = smc + 2 * AQB + (size_t)(kt & 1) * AKVST;
        const u32* KhW = (const u32*)(stb);
        const u32* KlW = (const u32*)(stb + 9216);
        const bf16* Vh = (const bf16*)(stb + 18432);
        const bf16* Vl = (const bf16*)(stb + 27648);

        // ---- S = Q K^T (split-3) ----
        float sacc[8][4];
#pragma unroll
        for (int nt = 0; nt < 8; nt++)
#pragma unroll
            for (int i = 0; i < 4; i++) sacc[nt][i] = 0.0f;

        const int qw = (w * 16 + g) * ASW + tq;
#pragma unroll
        for (int c = 0; c < 4; c++) {
            const int qo = qw + c * 8;
            const u32 ah0 = QhW[qo],     ah1 = QhW[qo + 8 * ASW];
            const u32 ah2 = QhW[qo + 4], ah3 = QhW[qo + 8 * ASW + 4];
            const u32 al0 = QlW[qo],     al1 = QlW[qo + 8 * ASW];
            const u32 al2 = QlW[qo + 4], al3 = QlW[qo + 8 * ASW + 4];
#pragma unroll
            for (int nt = 0; nt < 8; nt++) {
                const int ko = (nt * 8 + g) * ASW + tq + c * 8;
                const u32 bh0 = KhW[ko], bh1 = KhW[ko + 4];
                const u32 bl0 = KlW[ko], bl1 = KlW[ko + 4];
                mma16816(sacc[nt], ah0, ah1, ah2, ah3, bh0, bh1);
                mma16816(sacc[nt], ah0, ah1, ah2, ah3, bl0, bl1);
                mma16816(sacc[nt], al0, al1, al2, al3, bh0, bh1);
            }
        }

        // ---- online softmax ----
#pragma unroll
        for (int r = 0; r < 2; r++) {
            float rmax = -1e30f;
#pragma unroll
            for (int nt = 0; nt < 8; nt++)
                rmax = fmaxf(rmax, fmaxf(sacc[nt][2 * r], sacc[nt][2 * r + 1]));
            rmax = fmaxf(rmax, __shfl_xor_sync(0xffffffffu, rmax, 1));
            rmax = fmaxf(rmax, __shfl_xor_sync(0xffffffffu, rmax, 2));
            const float mn = fmaxf(mrow[r], rmax);
            const float corr = __expf(mrow[r] - mn);
            mrow[r] = mn;
            float rs = 0.0f;
#pragma unroll
            for (int nt = 0; nt < 8; nt++) {
                const float p0 = __expf(sacc[nt][2 * r] - mn);
                const float p1 = __expf(sacc[nt][2 * r + 1] - mn);
                sacc[nt][2 * r] = p0; sacc[nt][2 * r + 1] = p1;
                rs += p0 + p1;
            }
            rs += __shfl_xor_sync(0xffffffffu, rs, 1);
            rs += __shfl_xor_sync(0xffffffffu, rs, 2);
            lrow[r] = lrow[r] * corr + rs;
#pragma unroll
            for (int dt = 0; dt < 8; dt++) {
                oacc[dt][2 * r] *= corr; oacc[dt][2 * r + 1] *= corr;
            }
        }

        // ---- O += P V (split-3) ----
        const int vrow = lane & 15;
        const int vcol = (lane >> 4) << 3;
#pragma unroll
        for (int c = 0; c < 4; c++) {
            u32 ph[4], pl[4];
            {
                float p0 = sacc[2 * c][0], p1 = sacc[2 * c][1];
                ph[0] = packbf(p0, p1);
                pl[0] = packbf(p0 - bflo(ph[0]), p1 - bfhi(ph[0]));
                p0 = sacc[2 * c][2]; p1 = sacc[2 * c][3];
                ph[1] = packbf(p0, p1);
                pl[1] = packbf(p0 - bflo(ph[1]), p1 - bfhi(ph[1]));
                p0 = sacc[2 * c + 1][0]; p1 = sacc[2 * c + 1][1];
                ph[2] = packbf(p0, p1);
                pl[2] = packbf(p0 - bflo(ph[2]), p1 - bfhi(ph[2]));
                p0 = sacc[2 * c + 1][2]; p1 = sacc[2 * c + 1][3];
                ph[3] = packbf(p0, p1);
                pl[3] = packbf(p0 - bflo(ph[3]), p1 - bfhi(ph[3]));
            }
#pragma unroll
            for (int d2 = 0; d2 < 4; d2++) {
                u32 vh[4], vl[4];
                const int so = (c * 16 + vrow) * AS + d2 * 16 + vcol;
                ldsm4t(vh, &Vh[so]);
                ldsm4t(vl, &Vl[so]);
                mma16816(oacc[2 * d2],     ph[0], ph[1], ph[2], ph[3], vh[0], vh[1]);
                mma16816(oacc[2 * d2],     ph[0], ph[1], ph[2], ph[3], vl[0], vl[1]);
                mma16816(oacc[2 * d2],     pl[0], pl[1], pl[2], pl[3], vh[0], vh[1]);
                mma16816(oacc[2 * d2 + 1], ph[0], ph[1], ph[2], ph[3], vh[2], vh[3]);
                mma16816(oacc[2 * d2 + 1], ph[0], ph[1], ph[2], ph[3], vl[2], vl[3]);
                mma16816(oacc[2 * d2 + 1], pl[0], pl[1], pl[2], pl[3], vh[2], vh[3]);
            }
        }
        __syncthreads();
    }

    // ---- normalize + write bf16 hi/lo att ----
    const float inv0 = 1.0f / lrow[0];
    const float inv1 = 1.0f / lrow[1];
    const size_t row0 = (size_t)b * T_ + (size_t)qt * 128 + w * 16 + g;
    const size_t row1 = row0 + 8;
#pragma unroll
    for (int dt = 0; dt < 8; dt++) {
        const int col = h * D_ + dt * 8 + 2 * tq;
        const float a0 = oacc[dt][0] * inv0, a1 = oacc[dt][1] * inv0;
        const float b0 = oacc[dt][2] * inv1, b1 = oacc[dt][3] * inv1;
        const u32 h0 = packbf(a0, a1);
        const u32 l0 = packbf(a0 - bflo(h0), a1 - bfhi(h0));
        const u32 h1 = packbf(b0, b1);
        const u32 l1 = packbf(b0 - bflo(h1), b1 - bfhi(h1));
        *(u32*)&g_ath[row0 * E_ + col] = h0;
        *(u32*)&g_atl[row0 * E_ + col] = l0;
        *(u32*)&g_ath[row1 * E_ + col] = h1;
        *(u32*)&g_atl[row1 * E_ + col] = l1;
    }
}

// ---------------------------------------------------------------------------
extern "C" void kernel_launch(void* const* d_in, const int* in_sizes, int n_in,
                              void* d_out, int out_size) {
    const float *x = 0, *cosp = 0, *sinp = 0, *attn_w = 0, *proj_w = 0;
    for (int i = 0; i < n_in; i++) {
        const float* p = (const float*)d_in[i];
        switch (in_sizes[i]) {
            case 8388608: x = p; break;
            case 6291456: attn_w = p; break;
            case 4194304: proj_w = p; break;
            case 65536:   if (!cosp) cosp = p; else sinp = p; break;
            default: break;
        }
    }
    float* out = (float*)d_out;

    float* qkv;
    bf16 *xh, *xl, *awh, *awl, *pwh, *pwl, *ath, *atl;
    cudaGetSymbolAddress((void**)&qkv, g_qkv);
    cudaGetSymbolAddress((void**)&xh,  g_xh);  cudaGetSymbolAddress((void**)&xl,  g_xl);
    cudaGetSymbolAddress((void**)&awh, g_awh); cudaGetSymbolAddress((void**)&awl, g_awl);
    cudaGetSymbolAddress((void**)&pwh, g_pwh); cudaGetSymbolAddress((void**)&pwl, g_pwl);
    cudaGetSymbolAddress((void**)&ath, g_ath); cudaGetSymbolAddress((void**)&atl, g_atl);

    // 0) split fp32 inputs into bf16 hi/lo pairs
    split_kernel<<<(8388608 / 4 + 255) / 256, 256>>>((const float4*)x, xh, xl, 8388608 / 4);
    split_kernel<<<(6291456 / 4 + 255) / 256, 256>>>((const float4*)attn_w, awh, awl, 6291456 / 4);
    split_kernel<<<(4194304 / 4 + 255) / 256, 256>>>((const float4*)proj_w, pwh, pwl, 4194304 / 4);

    // 1) qkv = x @ attn_w^T
    cudaFuncSetAttribute((const void*)gemm_bf16_split,
                         cudaFuncAttributeMaxDynamicSharedMemorySize, GEMM_SMEM);
    gemm_bf16_split<<<dim3(QKV_F / 128, (B_ * T_) / 128), 256, GEMM_SMEM>>>(
        xh, xl, awh, awl, qkv, B_ * T_, QKV_F, E_);

    // 2) RoPE + GQA split -> bf16 hi/lo q/k/v
    const size_t total = (size_t)B_ * T_ * QKV_F;
    rope_split_kernel<<<(unsigned)((total + 255) / 256), 256>>>(cosp, sinp);

    // 3) attention
    cudaFuncSetAttribute((const void*)attn_mma_kernel,
                         cudaFuncAttributeMaxDynamicSharedMemorySize, AT_SMEM_BYTES);
    attn_mma_kernel<<<dim3(T_ / 128, H_, B_), 256, AT_SMEM_BYTES>>>();

    // 4) out = att @ proj_w^T
    gemm_bf16_split<<<dim3(E_ / 128, (B_ * T_) / 128), 256, GEMM_SMEM>>>(
        ath, atl, pwh, pwl, out, B_ * T_, E_, E_);
}

// round 9
// speedup vs baseline: 2.8630x; 1.0328x over previous
#include <cuda_runtime.h>
#include <cuda_bf16.h>
#include <math.h>

#define B_    2
#define T_    2048
#define E_    2048
#define H_    32
#define G_    8
#define D_    64
#define QKV_F 3072
#define QPK_  4

typedef __nv_bfloat16 bf16;
typedef unsigned int u32;

// ---------------- scratch (device globals; no allocation allowed) ----------
__device__ float g_qkv[(size_t)B_ * T_ * QKV_F];
__device__ bf16 g_xh [(size_t)B_ * T_ * E_],  g_xl [(size_t)B_ * T_ * E_];
__device__ bf16 g_awh[(size_t)QKV_F * E_],    g_awl[(size_t)QKV_F * E_];
__device__ bf16 g_pwh[(size_t)E_ * E_],       g_pwl[(size_t)E_ * E_];
__device__ bf16 g_qh [(size_t)B_ * H_ * T_ * D_], g_ql[(size_t)B_ * H_ * T_ * D_];
__device__ bf16 g_kh [(size_t)B_ * G_ * T_ * D_], g_kl[(size_t)B_ * G_ * T_ * D_];
__device__ bf16 g_vh [(size_t)B_ * G_ * T_ * D_], g_vl[(size_t)B_ * G_ * T_ * D_];
__device__ bf16 g_ath[(size_t)B_ * T_ * E_],  g_atl[(size_t)B_ * T_ * E_];

// ---------------- helpers --------------------------------------------------
__device__ __forceinline__ u32 packbf(float lo, float hi) {
    u32 r;
    asm("cvt.rn.bf16x2.f32 %0, %1, %2;" : "=r"(r) : "f"(hi), "f"(lo));
    return r;
}
__device__ __forceinline__ float bflo(u32 p) { return __uint_as_float(p << 16); }
__device__ __forceinline__ float bfhi(u32 p) { return __uint_as_float(p & 0xffff0000u); }

__device__ __forceinline__ void mma16816(float* c, u32 a0, u32 a1, u32 a2, u32 a3,
                                         u32 b0, u32 b1) {
    asm volatile(
        "mma.sync.aligned.m16n8k16.row.col.f32.bf16.bf16.f32 "
        "{%0,%1,%2,%3}, {%4,%5,%6,%7}, {%8,%9}, {%0,%1,%2,%3};"
        : "+f"(c[0]), "+f"(c[1]), "+f"(c[2]), "+f"(c[3])
        : "r"(a0), "r"(a1), "r"(a2), "r"(a3), "r"(b0), "r"(b1));
}

__device__ __forceinline__ void ldsm4(u32* r, u32 a) {
    asm volatile("ldmatrix.sync.aligned.m8n8.x4.shared.b16 {%0,%1,%2,%3}, [%4];"
                 : "=r"(r[0]), "=r"(r[1]), "=r"(r[2]), "=r"(r[3]) : "r"(a));
}
__device__ __forceinline__ void ldsm2(u32* r, u32 a) {
    asm volatile("ldmatrix.sync.aligned.m8n8.x2.shared.b16 {%0,%1}, [%2];"
                 : "=r"(r[0]), "=r"(r[1]) : "r"(a));
}
__device__ __forceinline__ void ldsm4t(u32* r, const bf16* p) {
    u32 a = (u32)__cvta_generic_to_shared(p);
    asm volatile("ldmatrix.sync.aligned.m8n8.x4.trans.shared.b16 {%0,%1,%2,%3}, [%4];"
                 : "=r"(r[0]), "=r"(r[1]), "=r"(r[2]), "=r"(r[3]) : "r"(a));
}

__device__ __forceinline__ u32 smem_u32(const void* p) {
    return (u32)__cvta_generic_to_shared(p);
}
__device__ __forceinline__ void cpasync16(u32 dst, const void* src) {
    asm volatile("cp.async.cg.shared.global [%0], [%1], 16;" :: "r"(dst), "l"(src));
}
__device__ __forceinline__ void cpcommit() { asm volatile("cp.async.commit_group;" ::: "memory"); }
__device__ __forceinline__ void cpwait0()  { asm volatile("cp.async.wait_group 0;" ::: "memory"); }
__device__ __forceinline__ void cpwait1()  { asm volatile("cp.async.wait_group 1;" ::: "memory"); }

// ---------------- split fp32 -> (hi, lo) bf16 ------------------------------
__global__ void split_kernel(const float4* __restrict__ s, bf16* __restrict__ h,
                             bf16* __restrict__ l, int n4) {
    int i = blockIdx.x * blockDim.x + threadIdx.x;
    if (i >= n4) return;
    float4 v = s[i];
    u32 h0 = packbf(v.x, v.y);
    u32 l0 = packbf(v.x - bflo(h0), v.y - bfhi(h0));
    u32 h1 = packbf(v.z, v.w);
    u32 l1 = packbf(v.z - bflo(h1), v.w - bfhi(h1));
    ((u32*)h)[2 * i] = h0; ((u32*)h)[2 * i + 1] = h1;
    ((u32*)l)[2 * i] = l0; ((u32*)l)[2 * i + 1] = l1;
}

// ===========================================================================
// GEMM (NT): C = (Ah+Al)(Bh+Bl)^T, split-3 bf16 HMMA.
// 128x128 tile, BK=64, 256 threads = 8 warps (4M x 2N), occ 1 (~200 regs).
// ldmatrix fragment loads + explicit frag double-buffer across 4 k16 slices.
// Stage: Ah@0 Al@18432 Bh@36864 Bl@55296, row stride 144B; 73728B/stage, x2.
// ===========================================================================
#define GROW 144
#define GST  73728
#define GEMM_SMEM (2 * GST)

struct FragC {          // frags for one k16 slice
    u32 ah[2][4], al[2][4];     // [mt][4]
    u32 bh[8][2], bl[8][2];     // [nt][2]
};

__device__ __forceinline__ void load_frags(FragC& f, u32 sbuf, int wm, int wn,
                                           int lane, int c) {
    // A: ldmatrix.x4, lanes: rows (l&7) + ((l>>3)&1)*8, chunk (l>>4)
    const u32 arow = (u32)(wm * 32 + (lane & 7) + ((lane >> 3) & 1) * 8);
    const u32 acb  = (u32)(c * 32 + (lane >> 4) * 16);
#pragma unroll
    for (int mt = 0; mt < 2; mt++) {
        const u32 a = sbuf + (arow + mt * 16) * GROW + acb;
        ldsm4(f.ah[mt], a);
        ldsm4(f.al[mt], a + 18432);
    }
    // B: ldmatrix.x2, lanes 0-15: rows nt*8+(l&7), chunk ((l>>3)&1)
    const u32 brow = (u32)(wn * 64 + (lane & 7));
    const u32 bcb  = (u32)(c * 32 + ((lane >> 3) & 1) * 16);
#pragma unroll
    for (int nt = 0; nt < 8; nt++) {
        const u32 a = sbuf + 36864 + (brow + nt * 8) * GROW + bcb;
        ldsm2(f.bh[nt], a);
        ldsm2(f.bl[nt], a + 18432);
    }
}

__device__ __forceinline__ void mma_frags(float acc[2][8][4], const FragC& f) {
#pragma unroll
    for (int nt = 0; nt < 8; nt++)      // term hi*hi
#pragma unroll
        for (int mt = 0; mt < 2; mt++)
            mma16816(acc[mt][nt], f.ah[mt][0], f.ah[mt][1], f.ah[mt][2], f.ah[mt][3],
                     f.bh[nt][0], f.bh[nt][1]);
#pragma unroll
    for (int nt = 0; nt < 8; nt++)      // term hi*lo
#pragma unroll
        for (int mt = 0; mt < 2; mt++)
            mma16816(acc[mt][nt], f.ah[mt][0], f.ah[mt][1], f.ah[mt][2], f.ah[mt][3],
                     f.bl[nt][0], f.bl[nt][1]);
#pragma unroll
    for (int nt = 0; nt < 8; nt++)      // term lo*hi
#pragma unroll
        for (int mt = 0; mt < 2; mt++)
            mma16816(acc[mt][nt], f.al[mt][0], f.al[mt][1], f.al[mt][2], f.al[mt][3],
                     f.bh[nt][0], f.bh[nt][1]);
}

__device__ __forceinline__ void stage_loads(
    const bf16* __restrict__ Ah, const bf16* __restrict__ Al,
    const bf16* __restrict__ Bh, const bf16* __restrict__ Bl,
    int K, int bm, int bn, int k0, u32 buf, int t) {
#pragma unroll
    for (int i = 0; i < 4; i++) {
        const int id = t + i * 256, row = id >> 3, cq = id & 7;
        const u32 d = buf + (u32)(row * GROW + cq * 16);
        const size_t ga = (size_t)(bm + row) * K + k0 + cq * 8;
        const size_t gb = (size_t)(bn + row) * K + k0 + cq * 8;
        cpasync16(d,         Ah + ga); cpasync16(d + 18432, Al + ga);
        cpasync16(d + 36864, Bh + gb); cpasync16(d + 55296, Bl + gb);
    }
}

__global__ __launch_bounds__(256, 1)
void gemm_bf16_split(const bf16* __restrict__ Ah, const bf16* __restrict__ Al,
                     const bf16* __restrict__ Bh, const bf16* __restrict__ Bl,
                     float* __restrict__ C, int M, int N, int K) {
    extern __shared__ char smc[];
    const u32 sb = smem_u32(smc);

    const int t = threadIdx.x, lane = t & 31, w = t >> 5;
    const int g = lane >> 2, tq = lane & 3;
    const int wm = w & 3, wn = w >> 2;
    const int bm = blockIdx.y * 128, bn = blockIdx.x * 128;

    float acc[2][8][4];
#pragma unroll
    for (int mt = 0; mt < 2; mt++)
#pragma unroll
        for (int nt = 0; nt < 8; nt++)
#pragma unroll
            for (int i = 0; i < 4; i++) acc[mt][nt][i] = 0.0f;

    const int NS = K / 64;

    stage_loads(Ah, Al, Bh, Bl, K, bm, bn, 0, sb, t);
    cpcommit();

    FragC fr[2];
    for (int s = 0; s < NS; s++) {
        if (s + 1 < NS) {
            stage_loads(Ah, Al, Bh, Bl, K, bm, bn, (s + 1) * 64,
                        sb + (u32)((s + 1) & 1) * GST, t);
            cpcommit();
            cpwait1();
        } else {
            cpwait0();
        }
        __syncthreads();

        const u32 sbuf = sb + (u32)(s & 1) * GST;
        load_frags(fr[0], sbuf, wm, wn, lane, 0);
#pragma unroll
        for (int c = 0; c < 4; c++) {
            if (c < 3) load_frags(fr[(c + 1) & 1], sbuf, wm, wn, lane, c + 1);
            mma_frags(acc, fr[c & 1]);
        }
        __syncthreads();
    }

#pragma unroll
    for (int mt = 0; mt < 2; mt++) {
        const int r0 = bm + wm * 32 + mt * 16 + g;
#pragma unroll
        for (int nt = 0; nt < 8; nt++) {
            const int cc = bn + wn * 64 + nt * 8 + 2 * tq;
            *(float2*)&C[(size_t)r0 * N + cc]       = make_float2(acc[mt][nt][0], acc[mt][nt][1]);
            *(float2*)&C[(size_t)(r0 + 8) * N + cc] = make_float2(acc[mt][nt][2], acc[mt][nt][3]);
        }
    }
}

// ---------------- RoPE + GQA split -> bf16 hi/lo ---------------------------
__global__ void rope_split_kernel(const float* __restrict__ cosp,
                                  const float* __restrict__ sinp) {
    size_t idx = (size_t)blockIdx.x * blockDim.x + threadIdx.x;
    const size_t total = (size_t)B_ * T_ * QKV_F;
    if (idx >= total) return;

    const int d = (int)(idx & 63);
    const int f = (int)(idx % QKV_F);
    const size_t bt = idx / QKV_F;
    const int tpos = (int)(bt % T_);
    const int b = (int)(bt / T_);
    const int g = f / 384;
    const int slot = (f % 384) >> 6;

    float val = g_qkv[idx];
    if (slot <= 4) {
        const int dh = d & 31;
        const float c = cosp[tpos * 32 + dh];
        const float s = sinp[tpos * 32 + dh];
        const float other = g_qkv[idx ^ 32];
        val = (d < 32) ? (val * c - other * s) : fmaf(val, c, other * s);
    }

    if (slot < QPK_) {
        val *= 0.125f;
        const int h = g * QPK_ + slot;
        const size_t o = (((size_t)b * H_ + h) * T_ + tpos) * D_ + d;
        bf16 hb = __float2bfloat16_rn(val);
        g_qh[o] = hb;
        g_ql[o] = __float2bfloat16_rn(val - __bfloat162float(hb));
    } else {
        const size_t o = (((size_t)b * G_ + g) * T_ + tpos) * D_ + d;
        bf16 hb = __float2bfloat16_rn(val);
        bf16 lb = __float2bfloat16_rn(val - __bfloat162float(hb));
        if (slot == QPK_) { g_kh[o] = hb; g_kl[o] = lb; }
        else              { g_vh[o] = hb; g_vl[o] = lb; }
    }
}

// ===========================================================================
// Flash attention, HMMA split-3, cp.async double-buffered K/V (round-5, passing)
// ===========================================================================
#define AS  72
#define ASW 36
#define AQB   18432
#define AKVST 36864
#define AT_SMEM_BYTES (2 * AQB + 2 * AKVST)

__global__ __launch_bounds__(256, 2) void attn_mma_kernel() {
    extern __shared__ char smc[];
    const u32 sb = smem_u32(smc);
    bf16* Qh = (bf16*)smc;
    bf16* Ql = (bf16*)(smc + AQB);
    u32* QhW = (u32*)Qh; u32* QlW = (u32*)Ql;

    const int t = threadIdx.x, lane = t & 31, w = t >> 5;
    const int g = lane >> 2, tq = lane & 3;
    const int qt = blockIdx.x, h = blockIdx.y, b = blockIdx.z, grp = h >> 2;

    {   // stage Q (128 x 64, hi+lo)
        const bf16* Qgh = g_qh + (((size_t)b * H_ + h) * T_ + (size_t)qt * 128) * D_;
        const bf16* Qgl = g_ql + (((size_t)b * H_ + h) * T_ + (size_t)qt * 128) * D_;
#pragma unroll
        for (int i = 0; i < 4; i++) {
            const int e = t + i * 256, row = e >> 3, c8 = (e & 7) * 8;
            *(uint4*)&Qh[row * AS + c8] = *(const uint4*)&Qgh[row * D_ + c8];
            *(uint4*)&Ql[row * AS + c8] = *(const uint4*)&Qgl[row * D_ + c8];
        }
    }

    float oacc[8][4];
#pragma unroll
    for (int dt = 0; dt < 8; dt++)
#pragma unroll
        for (int i = 0; i < 4; i++) oacc[dt][i] = 0.0f;
    float mrow[2] = {-1e30f, -1e30f};
    float lrow[2] = {0.0f, 0.0f};

    const size_t kvbase = ((size_t)b * G_ + grp) * T_ * D_;
    const int NKT = T_ / 64;

    {   // prologue: stage kt=0
        const u32 base = sb + 2 * AQB;
#pragma unroll
        for (int i = 0; i < 2; i++) {
            const int id = t + i * 256, row = id >> 3, cq = id & 7;
            const u32 d = base + (u32)(row * 144 + cq * 16);
            const size_t go = kvbase + (size_t)row * 64 + cq * 8;
            cpasync16(d,         g_kh + go); cpasync16(d + 9216,  g_kl + go);
            cpasync16(d + 18432, g_vh + go); cpasync16(d + 27648, g_vl + go);
        }
        cpcommit();
    }

    for (int kt = 0; kt < NKT; kt++) {
        if (kt + 1 < NKT) {
            const size_t kb = kvbase + (size_t)(kt + 1) * 64 * D_;
            const u32 base = sb + 2 * AQB + (u32)((kt + 1) & 1) * AKVST;
#pragma unroll
            for (int i = 0; i < 2; i++) {
                const int id = t + i * 256, row = id >> 3, cq = id & 7;
                const u32 d = base + (u32)(row * 144 + cq * 16);
                const size_t go = kb + (size_t)row * 64 + cq * 8;
                cpasync16(d,         g_kh + go); cpasync16(d + 9216,  g_kl + go);
                cpasync16(d + 18432, g_vh + go); cpasync16(d + 27648, g_vl + go);
            }
            cpcommit();
            cpwait1();
        } else {
            cpwait0();
        }
        __syncthreads();

        const char* stb = smc + 2 * AQB + (size_t)(kt & 1) * AKVST;
        const u32* KhW = (const u32*)(stb);
        const u32* KlW = (const u32*)(stb + 9216);
        const bf16* Vh = (const bf16*)(stb + 18432);
        const bf16* Vl = (const bf16*)(stb + 27648);

        float sacc[8][4];
#pragma unroll
        for (int nt = 0; nt < 8; nt++)
#pragma unroll
            for (int i = 0; i < 4; i++) sacc[nt][i] = 0.0f;

        const int qw = (w * 16 + g) * ASW + tq;
#pragma unroll
        for (int c = 0; c < 4; c++) {
            const int qo = qw + c * 8;
            const u32 ah0 = QhW[qo],     ah1 = QhW[qo + 8 * ASW];
            const u32 ah2 = QhW[qo + 4], ah3 = QhW[qo + 8 * ASW + 4];
            const u32 al0 = QlW[qo],     al1 = QlW[qo + 8 * ASW];
            const u32 al2 = QlW[qo + 4], al3 = QlW[qo + 8 * ASW + 4];
#pragma unroll
            for (int nt = 0; nt < 8; nt++) {
                const int ko = (nt * 8 + g) * ASW + tq + c * 8;
                const u32 bh0 = KhW[ko], bh1 = KhW[ko + 4];
                const u32 bl0 = KlW[ko], bl1 = KlW[ko + 4];
                mma16816(sacc[nt], ah0, ah1, ah2, ah3, bh0, bh1);
                mma16816(sacc[nt], ah0, ah1, ah2, ah3, bl0, bl1);
                mma16816(sacc[nt], al0, al1, al2, al3, bh0, bh1);
            }
        }

#pragma unroll
        for (int r = 0; r < 2; r++) {
            float rmax = -1e30f;
#pragma unroll
            for (int nt = 0; nt < 8; nt++)
                rmax = fmaxf(rmax, fmaxf(sacc[nt][2 * r], sacc[nt][2 * r + 1]));
            rmax = fmaxf(rmax, __shfl_xor_sync(0xffffffffu, rmax, 1));
            rmax = fmaxf(rmax, __shfl_xor_sync(0xffffffffu, rmax, 2));
            const float mn = fmaxf(mrow[r], rmax);
            const float corr = __expf(mrow[r] - mn);
            mrow[r] = mn;
            float rs = 0.0f;
#pragma unroll
            for (int nt = 0; nt < 8; nt++) {
                const float p0 = __expf(sacc[nt][2 * r] - mn);
                const float p1 = __expf(sacc[nt][2 * r + 1] - mn);
                sacc[nt][2 * r] = p0; sacc[nt][2 * r + 1] = p1;
                rs += p0 + p1;
            }
            rs += __shfl_xor_sync(0xffffffffu, rs, 1);
            rs += __shfl_xor_sync(0xffffffffu, rs, 2);
            lrow[r] = lrow[r] * corr + rs;
#pragma unroll
            for (int dt = 0; dt < 8; dt++) {
                oacc[dt][2 * r] *= corr; oacc[dt][2 * r + 1] *= corr;
            }
        }

        const int vrow = lane & 15;
        const int vcol = (lane >> 4) << 3;
#pragma unroll
        for (int c = 0; c < 4; c++) {
            u32 ph[4], pl[4];
            {
                float p0 = sacc[2 * c][0], p1 = sacc[2 * c][1];
                ph[0] = packbf(p0, p1);
                pl[0] = packbf(p0 - bflo(ph[0]), p1 - bfhi(ph[0]));
                p0 = sacc[2 * c][2]; p1 = sacc[2 * c][3];
                ph[1] = packbf(p0, p1);
                pl[1] = packbf(p0 - bflo(ph[1]), p1 - bfhi(ph[1]));
                p0 = sacc[2 * c + 1][0]; p1 = sacc[2 * c + 1][1];
                ph[2] = packbf(p0, p1);
                pl[2] = packbf(p0 - bflo(ph[2]), p1 - bfhi(ph[2]));
                p0 = sacc[2 * c + 1][2]; p1 = sacc[2 * c + 1][3];
                ph[3] = packbf(p0, p1);
                pl[3] = packbf(p0 - bflo(ph[3]), p1 - bfhi(ph[3]));
            }
#pragma unroll
            for (int d2 = 0; d2 < 4; d2++) {
                u32 vh[4], vl[4];
                const int so = (c * 16 + vrow) * AS + d2 * 16 + vcol;
                ldsm4t(vh, &Vh[so]);
                ldsm4t(vl, &Vl[so]);
                mma16816(oacc[2 * d2],     ph[0], ph[1], ph[2], ph[3], vh[0], vh[1]);
                mma16816(oacc[2 * d2],     ph[0], ph[1], ph[2], ph[3], vl[0], vl[1]);
                mma16816(oacc[2 * d2],     pl[0], pl[1], pl[2], pl[3], vh[0], vh[1]);
                mma16816(oacc[2 * d2 + 1], ph[0], ph[1], ph[2], ph[3], vh[2], vh[3]);
                mma16816(oacc[2 * d2 + 1], ph[0], ph[1], ph[2], ph[3], vl[2], vl[3]);
                mma16816(oacc[2 * d2 + 1], pl[0], pl[1], pl[2], pl[3], vh[2], vh[3]);
            }
        }
        __syncthreads();
    }

    const float inv0 = 1.0f / lrow[0];
    const float inv1 = 1.0f / lrow[1];
    const size_t row0 = (size_t)b * T_ + (size_t)qt * 128 + w * 16 + g;
    const size_t row1 = row0 + 8;
#pragma unroll
    for (int dt = 0; dt < 8; dt++) {
        const int col = h * D_ + dt * 8 + 2 * tq;
        const float a0 = oacc[dt][0] * inv0, a1 = oacc[dt][1] * inv0;
        const float b0 = oacc[dt][2] * inv1, b1 = oacc[dt][3] * inv1;
        const u32 h0 = packbf(a0, a1);
        const u32 l0 = packbf(a0 - bflo(h0), a1 - bfhi(h0));
        const u32 h1 = packbf(b0, b1);
        const u32 l1 = packbf(b0 - bflo(h1), b1 - bfhi(h1));
        *(u32*)&g_ath[row0 * E_ + col] = h0;
        *(u32*)&g_atl[row0 * E_ + col] = l0;
        *(u32*)&g_ath[row1 * E_ + col] = h1;
        *(u32*)&g_atl[row1 * E_ + col] = l1;
    }
}

// ---------------------------------------------------------------------------
extern "C" void kernel_launch(void* const* d_in, const int* in_sizes, int n_in,
                              void* d_out, int out_size) {
    const float *x = 0, *cosp = 0, *sinp = 0, *attn_w = 0, *proj_w = 0;
    for (int i = 0; i < n_in; i++) {
        const float* p = (const float*)d_in[i];
        switch (in_sizes[i]) {
            case 8388608: x = p; break;
            case 6291456: attn_w = p; break;
            case 4194304: proj_w = p; break;
            case 65536:   if (!cosp) cosp = p; else sinp = p; break;
            default: break;
        }
    }
    float* out = (float*)d_out;

    float* qkv;
    bf16 *xh, *xl, *awh, *awl, *pwh, *pwl, *ath, *atl;
    cudaGetSymbolAddress((void**)&qkv, g_qkv);
    cudaGetSymbolAddress((void**)&xh,  g_xh);  cudaGetSymbolAddress((void**)&xl,  g_xl);
    cudaGetSymbolAddress((void**)&awh, g_awh); cudaGetSymbolAddress((void**)&awl, g_awl);
    cudaGetSymbolAddress((void**)&pwh, g_pwh); cudaGetSymbolAddress((void**)&pwl, g_pwl);
    cudaGetSymbolAddress((void**)&ath, g_ath); cudaGetSymbolAddress((void**)&atl, g_atl);

    // 0) split fp32 inputs into bf16 hi/lo pairs
    split_kernel<<<(8388608 / 4 + 255) / 256, 256>>>((const float4*)x, xh, xl, 8388608 / 4);
    split_kernel<<<(6291456 / 4 + 255) / 256, 256>>>((const float4*)attn_w, awh, awl, 6291456 / 4);
    split_kernel<<<(4194304 / 4 + 255) / 256, 256>>>((const float4*)proj_w, pwh, pwl, 4194304 / 4);

    // 1) qkv = x @ attn_w^T
    cudaFuncSetAttribute((const void*)gemm_bf16_split,
                         cudaFuncAttributeMaxDynamicSharedMemorySize, GEMM_SMEM);
    gemm_bf16_split<<<dim3(QKV_F / 128, (B_ * T_) / 128), 256, GEMM_SMEM>>>(
        xh, xl, awh, awl, qkv, B_ * T_, QKV_F, E_);

    // 2) RoPE + GQA split -> bf16 hi/lo q/k/v
    const size_t total = (size_t)B_ * T_ * QKV_F;
    rope_split_kernel<<<(unsigned)((total + 255) / 256), 256>>>(cosp, sinp);

    // 3) attention
    cudaFuncSetAttribute((const void*)attn_mma_kernel,
                         cudaFuncAttributeMaxDynamicSharedMemorySize, AT_SMEM_BYTES);
    attn_mma_kernel<<<dim3(T_ / 128, H_, B_), 256, AT_SMEM_BYTES>>>();

    // 4) out = att @ proj_w^T
    gemm_bf16_split<<<dim3(E_ / 128, (B_ * T_) / 128), 256, GEMM_SMEM>>>(
        ath, atl, pwh, pwl, out, B_ * T_, E_, E_);
}

// round 10
// speedup vs baseline: 2.9831x; 1.0419x over previous
#include <cuda_runtime.h>
#include <cuda_bf16.h>
#include <math.h>

#define B_    2
#define T_    2048
#define E_    2048
#define H_    32
#define G_    8
#define D_    64
#define QKV_F 3072
#define QPK_  4

typedef __nv_bfloat16 bf16;
typedef unsigned int u32;

// ---------------- scratch (device globals; no allocation allowed) ----------
__device__ float g_qkv[(size_t)B_ * T_ * QKV_F];
__device__ bf16 g_xh [(size_t)B_ * T_ * E_],  g_xl [(size_t)B_ * T_ * E_];
__device__ bf16 g_awh[(size_t)QKV_F * E_],    g_awl[(size_t)QKV_F * E_];
__device__ bf16 g_pwh[(size_t)E_ * E_],       g_pwl[(size_t)E_ * E_];
__device__ bf16 g_qh [(size_t)B_ * H_ * T_ * D_], g_ql[(size_t)B_ * H_ * T_ * D_];
__device__ bf16 g_kh [(size_t)B_ * G_ * T_ * D_], g_kl[(size_t)B_ * G_ * T_ * D_];
__device__ bf16 g_vh [(size_t)B_ * G_ * T_ * D_], g_vl[(size_t)B_ * G_ * T_ * D_];
__device__ bf16 g_ath[(size_t)B_ * T_ * E_],  g_atl[(size_t)B_ * T_ * E_];

// ---------------- helpers --------------------------------------------------
__device__ __forceinline__ u32 packbf(float lo, float hi) {
    u32 r;
    asm("cvt.rn.bf16x2.f32 %0, %1, %2;" : "=r"(r) : "f"(hi), "f"(lo));
    return r;
}
__device__ __forceinline__ float bflo(u32 p) { return __uint_as_float(p << 16); }
__device__ __forceinline__ float bfhi(u32 p) { return __uint_as_float(p & 0xffff0000u); }

__device__ __forceinline__ void mma16816(float* c, u32 a0, u32 a1, u32 a2, u32 a3,
                                         u32 b0, u32 b1) {
    asm volatile(
        "mma.sync.aligned.m16n8k16.row.col.f32.bf16.bf16.f32 "
        "{%0,%1,%2,%3}, {%4,%5,%6,%7}, {%8,%9}, {%0,%1,%2,%3};"
        : "+f"(c[0]), "+f"(c[1]), "+f"(c[2]), "+f"(c[3])
        : "r"(a0), "r"(a1), "r"(a2), "r"(a3), "r"(b0), "r"(b1));
}

__device__ __forceinline__ void ldsm4(u32* r, u32 a) {
    asm volatile("ldmatrix.sync.aligned.m8n8.x4.shared.b16 {%0,%1,%2,%3}, [%4];"
                 : "=r"(r[0]), "=r"(r[1]), "=r"(r[2]), "=r"(r[3]) : "r"(a));
}
__device__ __forceinline__ void ldsm4t(u32* r, const bf16* p) {
    u32 a = (u32)__cvta_generic_to_shared(p);
    asm volatile("ldmatrix.sync.aligned.m8n8.x4.trans.shared.b16 {%0,%1,%2,%3}, [%4];"
                 : "=r"(r[0]), "=r"(r[1]), "=r"(r[2]), "=r"(r[3]) : "r"(a));
}

__device__ __forceinline__ u32 smem_u32(const void* p) {
    return (u32)__cvta_generic_to_shared(p);
}
__device__ __forceinline__ void cpasync16(u32 dst, const void* src) {
    asm volatile("cp.async.cg.shared.global [%0], [%1], 16;" :: "r"(dst), "l"(src));
}
__device__ __forceinline__ void cpcommit() { asm volatile("cp.async.commit_group;" ::: "memory"); }
__device__ __forceinline__ void cpwait0()  { asm volatile("cp.async.wait_group 0;" ::: "memory"); }
__device__ __forceinline__ void cpwait1()  { asm volatile("cp.async.wait_group 1;" ::: "memory"); }

// ---------------- split fp32 -> (hi, lo) bf16 ------------------------------
__global__ void split_kernel(const float4* __restrict__ s, bf16* __restrict__ h,
                             bf16* __restrict__ l, int n4) {
    int i = blockIdx.x * blockDim.x + threadIdx.x;
    if (i >= n4) return;
    float4 v = s[i];
    u32 h0 = packbf(v.x, v.y);
    u32 l0 = packbf(v.x - bflo(h0), v.y - bfhi(h0));
    u32 h1 = packbf(v.z, v.w);
    u32 l1 = packbf(v.z - bflo(h1), v.w - bfhi(h1));
    ((u32*)h)[2 * i] = h0; ((u32*)h)[2 * i + 1] = h1;
    ((u32*)l)[2 * i] = l0; ((u32*)l)[2 * i + 1] = l1;
}

// ===========================================================================
// GEMM (NT): C = (Ah+Al)(Bh+Bl)^T, split-3 bf16 HMMA.
// 128x256 CTA tile, BK=64, 512 threads = 16 warps (4M x 4N), warp tile 32x64.
// 4 warps/SMSP for latency hiding; ldsm4 for both A and paired-B frags.
// Stage: Ah@0(18432) Al@18432 Bh@36864(36864) Bl@73728; 110592B/stage, x2.
// ===========================================================================
#define GROW 144
#define GAST 18432
#define GBST 36864
#define GST  (2 * GAST + 2 * GBST)      // 110592
#define GEMM_SMEM (2 * GST)             // 221184

__device__ __forceinline__ void stage_loads(
    const bf16* __restrict__ Ah, const bf16* __restrict__ Al,
    const bf16* __restrict__ Bh, const bf16* __restrict__ Bl,
    int K, int bm, int bn, int k0, u32 buf, int t) {
#pragma unroll
    for (int i = 0; i < 2; i++) {       // A: 128 rows x 128B (h+l)
        const int id = t + i * 512, row = id >> 3, cq = id & 7;
        const u32 d = buf + (u32)(row * GROW + cq * 16);
        const size_t ga = (size_t)(bm + row) * K + k0 + cq * 8;
        cpasync16(d, Ah + ga); cpasync16(d + GAST, Al + ga);
    }
#pragma unroll
    for (int i = 0; i < 4; i++) {       // B: 256 rows x 128B (h+l)
        const int id = t + i * 512, row = id >> 3, cq = id & 7;
        const u32 d = buf + 2 * GAST + (u32)(row * GROW + cq * 16);
        const size_t gb = (size_t)(bn + row) * K + k0 + cq * 8;
        cpasync16(d, Bh + gb); cpasync16(d + GBST, Bl + gb);
    }
}

__global__ __launch_bounds__(512, 1)
void gemm_bf16_split(const bf16* __restrict__ Ah, const bf16* __restrict__ Al,
                     const bf16* __restrict__ Bh, const bf16* __restrict__ Bl,
                     float* __restrict__ C, int M, int N, int K) {
    extern __shared__ char smc[];
    const u32 sb = smem_u32(smc);

    const int t = threadIdx.x, lane = t & 31, w = t >> 5;
    const int g = lane >> 2, tq = lane & 3;
    const int wm = w & 3, wn = w >> 2;
    const int bm = blockIdx.y * 128, bn = blockIdx.x * 256;

    float acc[2][8][4];
#pragma unroll
    for (int mt = 0; mt < 2; mt++)
#pragma unroll
        for (int nt = 0; nt < 8; nt++)
#pragma unroll
            for (int i = 0; i < 4; i++) acc[mt][nt][i] = 0.0f;

    const int NS = K / 64;

    stage_loads(Ah, Al, Bh, Bl, K, bm, bn, 0, sb, t);
    cpcommit();

    // lane-invariant pieces of frag addresses
    const u32 arowl = (u32)(wm * 32 + (lane & 7) + ((lane >> 3) & 1) * 8);
    const u32 acoff = (u32)((lane >> 4) * 16);
    const u32 browl = (u32)(wn * 64 + (lane & 7) + ((lane >> 4) & 1) * 8);
    const u32 bcoff = (u32)(((lane >> 3) & 1) * 16);

    for (int s = 0; s < NS; s++) {
        if (s + 1 < NS) {
            stage_loads(Ah, Al, Bh, Bl, K, bm, bn, (s + 1) * 64,
                        sb + (u32)((s + 1) & 1) * GST, t);
            cpcommit();
            cpwait1();
        } else {
            cpwait0();
        }
        __syncthreads();

        const u32 sbuf = sb + (u32)(s & 1) * GST;
#pragma unroll
        for (int c = 0; c < 4; c++) {
            u32 ah[2][4], al[2][4], bh[8][2], bl[8][2];
            // A frags: 16x16 regions via ldsm4
#pragma unroll
            for (int mt = 0; mt < 2; mt++) {
                const u32 a = sbuf + (arowl + mt * 16) * GROW + c * 32 + acoff;
                ldsm4(ah[mt], a);
                ldsm4(al[mt], a + GAST);
            }
            // B frags: nt pairs via ldsm4 (m0=(nt,k0) m1=(nt,k1) m2=(nt+1,k0) m3=(nt+1,k1))
#pragma unroll
            for (int p = 0; p < 4; p++) {
                const u32 a = sbuf + 2 * GAST + (browl + p * 16) * GROW + c * 32 + bcoff;
                u32 r[4];
                ldsm4(r, a);
                bh[2 * p][0] = r[0]; bh[2 * p][1] = r[1];
                bh[2 * p + 1][0] = r[2]; bh[2 * p + 1][1] = r[3];
                ldsm4(r, a + GBST);
                bl[2 * p][0] = r[0]; bl[2 * p][1] = r[1];
                bl[2 * p + 1][0] = r[2]; bl[2 * p + 1][1] = r[3];
            }
            // term-major MMAs (accumulator reuse distance 16)
#pragma unroll
            for (int nt = 0; nt < 8; nt++)
#pragma unroll
                for (int mt = 0; mt < 2; mt++)
                    mma16816(acc[mt][nt], ah[mt][0], ah[mt][1], ah[mt][2], ah[mt][3],
                             bh[nt][0], bh[nt][1]);
#pragma unroll
            for (int nt = 0; nt < 8; nt++)
#pragma unroll
                for (int mt = 0; mt < 2; mt++)
                    mma16816(acc[mt][nt], ah[mt][0], ah[mt][1], ah[mt][2], ah[mt][3],
                             bl[nt][0], bl[nt][1]);
#pragma unroll
            for (int nt = 0; nt < 8; nt++)
#pragma unroll
                for (int mt = 0; mt < 2; mt++)
                    mma16816(acc[mt][nt], al[mt][0], al[mt][1], al[mt][2], al[mt][3],
                             bh[nt][0], bh[nt][1]);
        }
        __syncthreads();
    }

#pragma unroll
    for (int mt = 0; mt < 2; mt++) {
        const int r0 = bm + wm * 32 + mt * 16 + g;
#pragma unroll
        for (int nt = 0; nt < 8; nt++) {
            const int cc = bn + wn * 64 + nt * 8 + 2 * tq;
            *(float2*)&C[(size_t)r0 * N + cc]       = make_float2(acc[mt][nt][0], acc[mt][nt][1]);
            *(float2*)&C[(size_t)(r0 + 8) * N + cc] = make_float2(acc[mt][nt][2], acc[mt][nt][3]);
        }
    }
}

// ---------------- RoPE + GQA split -> bf16 hi/lo ---------------------------
__global__ void rope_split_kernel(const float* __restrict__ cosp,
                                  const float* __restrict__ sinp) {
    size_t idx = (size_t)blockIdx.x * blockDim.x + threadIdx.x;
    const size_t total = (size_t)B_ * T_ * QKV_F;
    if (idx >= total) return;

    const int d = (int)(idx & 63);
    const int f = (int)(idx % QKV_F);
    const size_t bt = idx / QKV_F;
    const int tpos = (int)(bt % T_);
    const int b = (int)(bt / T_);
    const int g = f / 384;
    const int slot = (f % 384) >> 6;

    float val = g_qkv[idx];
    if (slot <= 4) {
        const int dh = d & 31;
        const float c = cosp[tpos * 32 + dh];
        const float s = sinp[tpos * 32 + dh];
        const float other = g_qkv[idx ^ 32];
        val = (d < 32) ? (val * c - other * s) : fmaf(val, c, other * s);
    }

    if (slot < QPK_) {
        val *= 0.125f;
        const int h = g * QPK_ + slot;
        const size_t o = (((size_t)b * H_ + h) * T_ + tpos) * D_ + d;
        bf16 hb = __float2bfloat16_rn(val);
        g_qh[o] = hb;
        g_ql[o] = __float2bfloat16_rn(val - __bfloat162float(hb));
    } else {
        const size_t o = (((size_t)b * G_ + g) * T_ + tpos) * D_ + d;
        bf16 hb = __float2bfloat16_rn(val);
        bf16 lb = __float2bfloat16_rn(val - __bfloat162float(hb));
        if (slot == QPK_) { g_kh[o] = hb; g_kl[o] = lb; }
        else              { g_vh[o] = hb; g_vl[o] = lb; }
    }
}

// ===========================================================================
// Flash attention, HMMA split-3, cp.async double-buffered K/V (passing)
// ===========================================================================
#define AS  72
#define ASW 36
#define AQB   18432
#define AKVST 36864
#define AT_SMEM_BYTES (2 * AQB + 2 * AKVST)

__global__ __launch_bounds__(256, 2) void attn_mma_kernel() {
    extern __shared__ char smc[];
    const u32 sb = smem_u32(smc);
    bf16* Qh = (bf16*)smc;
    bf16* Ql = (bf16*)(smc + AQB);
    u32* QhW = (u32*)Qh; u32* QlW = (u32*)Ql;

    const int t = threadIdx.x, lane = t & 31, w = t >> 5;
    const int g = lane >> 2, tq = lane & 3;
    const int qt = blockIdx.x, h = blockIdx.y, b = blockIdx.z, grp = h >> 2;

    {   // stage Q (128 x 64, hi+lo)
        const bf16* Qgh = g_qh + (((size_t)b * H_ + h) * T_ + (size_t)qt * 128) * D_;
        const bf16* Qgl = g_ql + (((size_t)b * H_ + h) * T_ + (size_t)qt * 128) * D_;
#pragma unroll
        for (int i = 0; i < 4; i++) {
            const int e = t + i * 256, row = e >> 3, c8 = (e & 7) * 8;
            *(uint4*)&Qh[row * AS + c8] = *(const uint4*)&Qgh[row * D_ + c8];
            *(uint4*)&Ql[row * AS + c8] = *(const uint4*)&Qgl[row * D_ + c8];
        }
    }

    float oacc[8][4];
#pragma unroll
    for (int dt = 0; dt < 8; dt++)
#pragma unroll
        for (int i = 0; i < 4; i++) oacc[dt][i] = 0.0f;
    float mrow[2] = {-1e30f, -1e30f};
    float lrow[2] = {0.0f, 0.0f};

    const size_t kvbase = ((size_t)b * G_ + grp) * T_ * D_;
    const int NKT = T_ / 64;

    {   // prologue: stage kt=0
        const u32 base = sb + 2 * AQB;
#pragma unroll
        for (int i = 0; i < 2; i++) {
            const int id = t + i * 256, row = id >> 3, cq = id & 7;
            const u32 d = base + (u32)(row * 144 + cq * 16);
            const size_t go = kvbase + (size_t)row * 64 + cq * 8;
            cpasync16(d,         g_kh + go); cpasync16(d + 9216,  g_kl + go);
            cpasync16(d + 18432, g_vh + go); cpasync16(d + 27648, g_vl + go);
        }
        cpcommit();
    }

    for (int kt = 0; kt < NKT; kt++) {
        if (kt + 1 < NKT) {
            const size_t kb = kvbase + (size_t)(kt + 1) * 64 * D_;
            const u32 base = sb + 2 * AQB + (u32)((kt + 1) & 1) * AKVST;
#pragma unroll
            for (int i = 0; i < 2; i++) {
                const int id = t + i * 256, row = id >> 3, cq = id & 7;
                const u32 d = base + (u32)(row * 144 + cq * 16);
                const size_t go = kb + (size_t)row * 64 + cq * 8;
                cpasync16(d,         g_kh + go); cpasync16(d + 9216,  g_kl + go);
                cpasync16(d + 18432, g_vh + go); cpasync16(d + 27648, g_vl + go);
            }
            cpcommit();
            cpwait1();
        } else {
            cpwait0();
        }
        __syncthreads();

        const char* stb = smc + 2 * AQB + (size_t)(kt & 1) * AKVST;
        const u32* KhW = (const u32*)(stb);
        const u32* KlW = (const u32*)(stb + 9216);
        const bf16* Vh = (const bf16*)(stb + 18432);
        const bf16* Vl = (const bf16*)(stb + 27648);

        float sacc[8][4];
#pragma unroll
        for (int nt = 0; nt < 8; nt++)
#pragma unroll
            for (int i = 0; i < 4; i++) sacc[nt][i] = 0.0f;

        const int qw = (w * 16 + g) * ASW + tq;
#pragma unroll
        for (int c = 0; c < 4; c++) {
            const int qo = qw + c * 8;
            const u32 ah0 = QhW[qo],     ah1 = QhW[qo + 8 * ASW];
            const u32 ah2 = QhW[qo + 4], ah3 = QhW[qo + 8 * ASW + 4];
            const u32 al0 = QlW[qo],     al1 = QlW[qo + 8 * ASW];
            const u32 al2 = QlW[qo + 4], al3 = QlW[qo + 8 * ASW + 4];
#pragma unroll
            for (int nt = 0; nt < 8; nt++) {
                const int ko = (nt * 8 + g) * ASW + tq + c * 8;
                const u32 bh0 = KhW[ko], bh1 = KhW[ko + 4];
                const u32 bl0 = KlW[ko], bl1 = KlW[ko + 4];
                mma16816(sacc[nt], ah0, ah1, ah2, ah3, bh0, bh1);
                mma16816(sacc[nt], ah0, ah1, ah2, ah3, bl0, bl1);
                mma16816(sacc[nt], al0, al1, al2, al3, bh0, bh1);
            }
        }

#pragma unroll
        for (int r = 0; r < 2; r++) {
            float rmax = -1e30f;
#pragma unroll
            for (int nt = 0; nt < 8; nt++)
                rmax = fmaxf(rmax, fmaxf(sacc[nt][2 * r], sacc[nt][2 * r + 1]));
            rmax = fmaxf(rmax, __shfl_xor_sync(0xffffffffu, rmax, 1));
            rmax = fmaxf(rmax, __shfl_xor_sync(0xffffffffu, rmax, 2));
            const float mn = fmaxf(mrow[r], rmax);
            const float corr = __expf(mrow[r] - mn);
            mrow[r] = mn;
            float rs = 0.0f;
#pragma unroll
            for (int nt = 0; nt < 8; nt++) {
                const float p0 = __expf(sacc[nt][2 * r] - mn);
                const float p1 = __expf(sacc[nt][2 * r + 1] - mn);
                sacc[nt][2 * r] = p0; sacc[nt][2 * r + 1] = p1;
                rs += p0 + p1;
            }
            rs += __shfl_xor_sync(0xffffffffu, rs, 1);
            rs += __shfl_xor_sync(0xffffffffu, rs, 2);
            lrow[r] = lrow[r] * corr + rs;
#pragma unroll
            for (int dt = 0; dt < 8; dt++) {
                oacc[dt][2 * r] *= corr; oacc[dt][2 * r + 1] *= corr;
            }
        }

        const int vrow = lane & 15;
        const int vcol = (lane >> 4) << 3;
#pragma unroll
        for (int c = 0; c < 4; c++) {
            u32 ph[4], pl[4];
            {
                float p0 = sacc[2 * c][0], p1 = sacc[2 * c][1];
                ph[0] = packbf(p0, p1);
                pl[0] = packbf(p0 - bflo(ph[0]), p1 - bfhi(ph[0]));
                p0 = sacc[2 * c][2]; p1 = sacc[2 * c][3];
                ph[1] = packbf(p0, p1);
                pl[1] = packbf(p0 - bflo(ph[1]), p1 - bfhi(ph[1]));
                p0 = sacc[2 * c + 1][0]; p1 = sacc[2 * c + 1][1];
                ph[2] = packbf(p0, p1);
                pl[2] = packbf(p0 - bflo(ph[2]), p1 - bfhi(ph[2]));
                p0 = sacc[2 * c + 1][2]; p1 = sacc[2 * c + 1][3];
                ph[3] = packbf(p0, p1);
                pl[3] = packbf(p0 - bflo(ph[3]), p1 - bfhi(ph[3]));
            }
#pragma unroll
            for (int d2 = 0; d2 < 4; d2++) {
                u32 vh[4], vl[4];
                const int so = (c * 16 + vrow) * AS + d2 * 16 + vcol;
                ldsm4t(vh, &Vh[so]);
                ldsm4t(vl, &Vl[so]);
                mma16816(oacc[2 * d2],     ph[0], ph[1], ph[2], ph[3], vh[0], vh[1]);
                mma16816(oacc[2 * d2],     ph[0], ph[1], ph[2], ph[3], vl[0], vl[1]);
                mma16816(oacc[2 * d2],     pl[0], pl[1], pl[2], pl[3], vh[0], vh[1]);
                mma16816(oacc[2 * d2 + 1], ph[0], ph[1], ph[2], ph[3], vh[2], vh[3]);
                mma16816(oacc[2 * d2 + 1], ph[0], ph[1], ph[2], ph[3], vl[2], vl[3]);
                mma16816(oacc[2 * d2 + 1], pl[0], pl[1], pl[2], pl[3], vh[2], vh[3]);
            }
        }
        __syncthreads();
    }

    const float inv0 = 1.0f / lrow[0];
    const float inv1 = 1.0f / lrow[1];
    const size_t row0 = (size_t)b * T_ + (size_t)qt * 128 + w * 16 + g;
    const size_t row1 = row0 + 8;
#pragma unroll
    for (int dt = 0; dt < 8; dt++) {
        const int col = h * D_ + dt * 8 + 2 * tq;
        const float a0 = oacc[dt][0] * inv0, a1 = oacc[dt][1] * inv0;
        const float b0 = oacc[dt][2] * inv1, b1 = oacc[dt][3] * inv1;
        const u32 h0 = packbf(a0, a1);
        const u32 l0 = packbf(a0 - bflo(h0), a1 - bfhi(h0));
        const u32 h1 = packbf(b0, b1);
        const u32 l1 = packbf(b0 - bflo(h1), b1 - bfhi(h1));
        *(u32*)&g_ath[row0 * E_ + col] = h0;
        *(u32*)&g_atl[row0 * E_ + col] = l0;
        *(u32*)&g_ath[row1 * E_ + col] = h1;
        *(u32*)&g_atl[row1 * E_ + col] = l1;
    }
}

// ---------------------------------------------------------------------------
extern "C" void kernel_launch(void* const* d_in, const int* in_sizes, int n_in,
                              void* d_out, int out_size) {
    const float *x = 0, *cosp = 0, *sinp = 0, *attn_w = 0, *proj_w = 0;
    for (int i = 0; i < n_in; i++) {
        const float* p = (const float*)d_in[i];
        switch (in_sizes[i]) {
            case 8388608: x = p; break;
            case 6291456: attn_w = p; break;
            case 4194304: proj_w = p; break;
            case 65536:   if (!cosp) cosp = p; else sinp = p; break;
            default: break;
        }
    }
    float* out = (float*)d_out;

    float* qkv;
    bf16 *xh, *xl, *awh, *awl, *pwh, *pwl, *ath, *atl;
    cudaGetSymbolAddress((void**)&qkv, g_qkv);
    cudaGetSymbolAddress((void**)&xh,  g_xh);  cudaGetSymbolAddress((void**)&xl,  g_xl);
    cudaGetSymbolAddress((void**)&awh, g_awh); cudaGetSymbolAddress((void**)&awl, g_awl);
    cudaGetSymbolAddress((void**)&pwh, g_pwh); cudaGetSymbolAddress((void**)&pwl, g_pwl);
    cudaGetSymbolAddress((void**)&ath, g_ath); cudaGetSymbolAddress((void**)&atl, g_atl);

    // 0) split fp32 inputs into bf16 hi/lo pairs
    split_kernel<<<(8388608 / 4 + 255) / 256, 256>>>((const float4*)x, xh, xl, 8388608 / 4);
    split_kernel<<<(6291456 / 4 + 255) / 256, 256>>>((const float4*)attn_w, awh, awl, 6291456 / 4);
    split_kernel<<<(4194304 / 4 + 255) / 256, 256>>>((const float4*)proj_w, pwh, pwl, 4194304 / 4);

    // 1) qkv = x @ attn_w^T   (M=4096, N=3072, K=2048)
    cudaFuncSetAttribute((const void*)gemm_bf16_split,
                         cudaFuncAttributeMaxDynamicSharedMemorySize, GEMM_SMEM);
    gemm_bf16_split<<<dim3(QKV_F / 256, (B_ * T_) / 128), 512, GEMM_SMEM>>>(
        xh, xl, awh, awl, qkv, B_ * T_, QKV_F, E_);

    // 2) RoPE + GQA split -> bf16 hi/lo q/k/v
    const size_t total = (size_t)B_ * T_ * QKV_F;
    rope_split_kernel<<<(unsigned)((total + 255) / 256), 256>>>(cosp, sinp);

    // 3) attention
    cudaFuncSetAttribute((const void*)attn_mma_kernel,
                         cudaFuncAttributeMaxDynamicSharedMemorySize, AT_SMEM_BYTES);
    attn_mma_kernel<<<dim3(T_ / 128, H_, B_), 256, AT_SMEM_BYTES>>>();

    // 4) out = att @ proj_w^T   (M=4096, N=2048, K=2048)
    gemm_bf16_split<<<dim3(E_ / 256, (B_ * T_) / 128), 512, GEMM_SMEM>>>(
        ath, atl, pwh, pwl, out, B_ * T_, E_, E_);
}

// round 12
// speedup vs baseline: 3.9845x; 1.3357x over previous
#include <cuda_runtime.h>
#include <cuda_fp16.h>
#include <math.h>

#define B_    2
#define T_    2048
#define E_    2048
#define H_    32
#define G_    8
#define D_    64
#define QKV_F 3072
#define QPK_  4

typedef unsigned int u32;

// ---------------- scratch (device globals; no allocation allowed) ----------
__device__ float g_qkv[(size_t)B_ * T_ * QKV_F];
__device__ __half g_xh [(size_t)B_ * T_ * E_];
__device__ __half g_awh[(size_t)QKV_F * E_], g_awl[(size_t)QKV_F * E_];
__device__ __half g_pwh[(size_t)E_ * E_],    g_pwl[(size_t)E_ * E_];
__device__ __half g_qh [(size_t)B_ * H_ * T_ * D_];
__device__ __half g_kh [(size_t)B_ * G_ * T_ * D_], g_kl[(size_t)B_ * G_ * T_ * D_];
__device__ __half g_vh [(size_t)B_ * G_ * T_ * D_], g_vl[(size_t)B_ * G_ * T_ * D_];
__device__ __half g_ath[(size_t)B_ * T_ * E_];

// ---------------- helpers --------------------------------------------------
__device__ __forceinline__ u32 packh(float lo, float hi) {
    u32 r;
    asm("cvt.rn.f16x2.f32 %0, %1, %2;" : "=r"(r) : "f"(hi), "f"(lo));
    return r;
}

__device__ __forceinline__ void mma16816(float* c, u32 a0, u32 a1, u32 a2, u32 a3,
                                         u32 b0, u32 b1) {
    asm volatile(
        "mma.sync.aligned.m16n8k16.row.col.f32.f16.f16.f32 "
        "{%0,%1,%2,%3}, {%4,%5,%6,%7}, {%8,%9}, {%0,%1,%2,%3};"
        : "+f"(c[0]), "+f"(c[1]), "+f"(c[2]), "+f"(c[3])
        : "r"(a0), "r"(a1), "r"(a2), "r"(a3), "r"(b0), "r"(b1));
}

__device__ __forceinline__ void ldsm4(u32* r, u32 a) {
    asm volatile("ldmatrix.sync.aligned.m8n8.x4.shared.b16 {%0,%1,%2,%3}, [%4];"
                 : "=r"(r[0]), "=r"(r[1]), "=r"(r[2]), "=r"(r[3]) : "r"(a));
}
__device__ __forceinline__ void ldsm4t(u32* r, const __half* p) {
    u32 a = (u32)__cvta_generic_to_shared(p);
    asm volatile("ldmatrix.sync.aligned.m8n8.x4.trans.shared.b16 {%0,%1,%2,%3}, [%4];"
                 : "=r"(r[0]), "=r"(r[1]), "=r"(r[2]), "=r"(r[3]) : "r"(a));
}

__device__ __forceinline__ u32 smem_u32(const void* p) {
    return (u32)__cvta_generic_to_shared(p);
}
__device__ __forceinline__ void cpasync16(u32 dst, const void* src) {
    asm volatile("cp.async.cg.shared.global [%0], [%1], 16;" :: "r"(dst), "l"(src));
}
__device__ __forceinline__ void cpcommit() { asm volatile("cp.async.commit_group;" ::: "memory"); }
__device__ __forceinline__ void cpwait0()  { asm volatile("cp.async.wait_group 0;" ::: "memory"); }
__device__ __forceinline__ void cpwait1()  { asm volatile("cp.async.wait_group 1;" ::: "memory"); }

// ---------------- split kernels --------------------------------------------
// hi-only: fp32 -> fp16 (activation side; dropped-lo error ~2^-12.6 per GEMM)
__global__ void split_hi_kernel(const float4* __restrict__ s, __half* __restrict__ h,
                                int n4) {
    int i = blockIdx.x * blockDim.x + threadIdx.x;
    if (i >= n4) return;
    float4 v = s[i];
    ((u32*)h)[2 * i]     = packh(v.x, v.y);
    ((u32*)h)[2 * i + 1] = packh(v.z, v.w);
}

// hi+lo: fp32 -> fp16 pair (weight side; error 2^-22)
__global__ void split2_kernel(const float4* __restrict__ s, __half* __restrict__ h,
                              __half* __restrict__ l, int n4) {
    int i = blockIdx.x * blockDim.x + threadIdx.x;
    if (i >= n4) return;
    float4 v = s[i];
    __half hx = __float2half_rn(v.x), hy = __float2half_rn(v.y);
    __half hz = __float2half_rn(v.z), hw = __float2half_rn(v.w);
    ((u32*)h)[2 * i]     = ((u32)__half_as_ushort(hy) << 16) | __half_as_ushort(hx);
    ((u32*)h)[2 * i + 1] = ((u32)__half_as_ushort(hw) << 16) | __half_as_ushort(hz);
    ((u32*)l)[2 * i]     = packh(v.x - __half2float(hx), v.y - __half2float(hy));
    ((u32*)l)[2 * i + 1] = packh(v.z - __half2float(hz), v.w - __half2float(hw));
}

// ===========================================================================
// GEMM (NT): C = Ah (Bh+Bl)^T, 2-term fp16 HMMA.
// 128x256 CTA tile, BK=64, 512 threads = 16 warps (4M x 4N), warp tile 32x64.
// Stage: Ah@0 (18432) | Bh@18432 (36864) | Bl@55296 (36864) = 92160 B, x2.
// ===========================================================================
#define GROW 144
#define GAST 18432
#define GBST 36864
#define GST  (GAST + 2 * GBST)          // 92160
#define GEMM_SMEM (2 * GST)             // 184320

__device__ __forceinline__ void stage_loads(
    const __half* __restrict__ Ah,
    const __half* __restrict__ Bh, const __half* __restrict__ Bl,
    int K, int bm, int bn, int k0, u32 buf, int t) {
#pragma unroll
    for (int i = 0; i < 2; i++) {       // A: 128 rows x 128B
        const int id = t + i * 512, row = id >> 3, cq = id & 7;
        const u32 d = buf + (u32)(row * GROW + cq * 16);
        cpasync16(d, Ah + (size_t)(bm + row) * K + k0 + cq * 8);
    }
#pragma unroll
    for (int i = 0; i < 4; i++) {       // B: 256 rows x 128B (h+l)
        const int id = t + i * 512, row = id >> 3, cq = id & 7;
        const u32 d = buf + GAST + (u32)(row * GROW + cq * 16);
        const size_t gb = (size_t)(bn + row) * K + k0 + cq * 8;
        cpasync16(d, Bh + gb); cpasync16(d + GBST, Bl + gb);
    }
}

__global__ __launch_bounds__(512, 1)
void gemm_f16_2t(const __half* __restrict__ Ah,
                 const __half* __restrict__ Bh, const __half* __restrict__ Bl,
                 float* __restrict__ C, int M, int N, int K) {
    extern __shared__ char smc[];
    const u32 sb = smem_u32(smc);

    const int t = threadIdx.x, lane = t & 31, w = t >> 5;
    const int g = lane >> 2, tq = lane & 3;
    const int wm = w & 3, wn = w >> 2;
    const int bm = blockIdx.y * 128, bn = blockIdx.x * 256;

    float acc[2][8][4];
#pragma unroll
    for (int mt = 0; mt < 2; mt++)
#pragma unroll
        for (int nt = 0; nt < 8; nt++)
#pragma unroll
            for (int i = 0; i < 4; i++) acc[mt][nt][i] = 0.0f;

    const int NS = K / 64;

    stage_loads(Ah, Bh, Bl, K, bm, bn, 0, sb, t);
    cpcommit();

    const u32 arowl = (u32)(wm * 32 + (lane & 7) + ((lane >> 3) & 1) * 8);
    const u32 acoff = (u32)((lane >> 4) * 16);
    const u32 browl = (u32)(wn * 64 + (lane & 7) + ((lane >> 4) & 1) * 8);
    const u32 bcoff = (u32)(((lane >> 3) & 1) * 16);

    for (int s = 0; s < NS; s++) {
        if (s + 1 < NS) {
            stage_loads(Ah, Bh, Bl, K, bm, bn, (s + 1) * 64,
                        sb + (u32)((s + 1) & 1) * GST, t);
            cpcommit();
            cpwait1();
        } else {
            cpwait0();
        }
        __syncthreads();

        const u32 sbuf = sb + (u32)(s & 1) * GST;
#pragma unroll
        for (int c = 0; c < 4; c++) {
            u32 ah[2][4], bh[8][2], bl[8][2];
#pragma unroll
            for (int mt = 0; mt < 2; mt++)
                ldsm4(ah[mt], sbuf + (arowl + mt * 16) * GROW + c * 32 + acoff);
#pragma unroll
            for (int p = 0; p < 4; p++) {
                const u32 a = sbuf + GAST + (browl + p * 16) * GROW + c * 32 + bcoff;
                u32 r[4];
                ldsm4(r, a);
                bh[2 * p][0] = r[0]; bh[2 * p][1] = r[1];
                bh[2 * p + 1][0] = r[2]; bh[2 * p + 1][1] = r[3];
                ldsm4(r, a + GBST);
                bl[2 * p][0] = r[0]; bl[2 * p][1] = r[1];
                bl[2 * p + 1][0] = r[2]; bl[2 * p + 1][1] = r[3];
            }
#pragma unroll
            for (int nt = 0; nt < 8; nt++)
#pragma unroll
                for (int mt = 0; mt < 2; mt++)
                    mma16816(acc[mt][nt], ah[mt][0], ah[mt][1], ah[mt][2], ah[mt][3],
                             bh[nt][0], bh[nt][1]);
#pragma unroll
            for (int nt = 0; nt < 8; nt++)
#pragma unroll
                for (int mt = 0; mt < 2; mt++)
                    mma16816(acc[mt][nt], ah[mt][0], ah[mt][1], ah[mt][2], ah[mt][3],
                             bl[nt][0], bl[nt][1]);
        }
        __syncthreads();
    }

#pragma unroll
    for (int mt = 0; mt < 2; mt++) {
        const int r0 = bm + wm * 32 + mt * 16 + g;
#pragma unroll
        for (int nt = 0; nt < 8; nt++) {
            const int cc = bn + wn * 64 + nt * 8 + 2 * tq;
            *(float2*)&C[(size_t)r0 * N + cc]       = make_float2(acc[mt][nt][0], acc[mt][nt][1]);
            *(float2*)&C[(size_t)(r0 + 8) * N + cc] = make_float2(acc[mt][nt][2], acc[mt][nt][3]);
        }
    }
}

// ---------------- RoPE + GQA split -> fp16 ---------------------------------
__global__ void rope_split_kernel(const float* __restrict__ cosp,
                                  const float* __restrict__ sinp) {
    size_t idx = (size_t)blockIdx.x * blockDim.x + threadIdx.x;
    const size_t total = (size_t)B_ * T_ * QKV_F;
    if (idx >= total) return;

    const int d = (int)(idx & 63);
    const int f = (int)(idx % QKV_F);
    const size_t bt = idx / QKV_F;
    const int tpos = (int)(bt % T_);
    const int b = (int)(bt / T_);
    const int g = f / 384;
    const int slot = (f % 384) >> 6;

    float val = g_qkv[idx];
    if (slot <= 4) {
        const int dh = d & 31;
        const float c = cosp[tpos * 32 + dh];
        const float s = sinp[tpos * 32 + dh];
        const float other = g_qkv[idx ^ 32];
        val = (d < 32) ? (val * c - other * s) : fmaf(val, c, other * s);
    }

    if (slot < QPK_) {
        val *= 0.125f;
        const int h = g * QPK_ + slot;
        g_qh[(((size_t)b * H_ + h) * T_ + tpos) * D_ + d] = __float2half_rn(val);
    } else {
        const size_t o = (((size_t)b * G_ + g) * T_ + tpos) * D_ + d;
        __half hb = __float2half_rn(val);
        __half lb = __float2half_rn(val - __half2float(hb));
        if (slot == QPK_) { g_kh[o] = hb; g_kl[o] = lb; }
        else              { g_vh[o] = hb; g_vl[o] = lb; }
    }
}

// ===========================================================================
// Flash attention, fp16 HMMA 2-term: S = Qh(Kh+Kl)^T, O += Ph(Vh+Vl).
// Block (b,h,128 q rows), 256 threads = 8 warps, kv tile 64, 2-stage cp.async.
// smem: Qh @0 (18432); stage @18432 + st*36864: Kh+0 Kl+9216 Vh+18432 Vl+27648.
// ===========================================================================
#define AS  72
#define ASW 36
#define AQB   18432
#define AKVST 36864
#define AT_SMEM_BYTES (AQB + 2 * AKVST)     // 92160

__global__ __launch_bounds__(256, 2) void attn_mma_kernel() {
    extern __shared__ char smc[];
    const u32 sb = smem_u32(smc);
    __half* Qh = (__half*)smc;
    u32* QhW = (u32*)Qh;

    const int t = threadIdx.x, lane = t & 31, w = t >> 5;
    const int g = lane >> 2, tq = lane & 3;
    const int qt = blockIdx.x, h = blockIdx.y, b = blockIdx.z, grp = h >> 2;

    {   // stage Q (128 x 64 hi)
        const __half* Qg = g_qh + (((size_t)b * H_ + h) * T_ + (size_t)qt * 128) * D_;
#pragma unroll
        for (int i = 0; i < 4; i++) {
            const int e = t + i * 256, row = e >> 3, c8 = (e & 7) * 8;
            *(uint4*)&Qh[row * AS + c8] = *(const uint4*)&Qg[row * D_ + c8];
        }
    }

    float oacc[8][4];
#pragma unroll
    for (int dt = 0; dt < 8; dt++)
#pragma unroll
        for (int i = 0; i < 4; i++) oacc[dt][i] = 0.0f;
    float mrow[2] = {-1e30f, -1e30f};
    float lrow[2] = {0.0f, 0.0f};

    const size_t kvbase = ((size_t)b * G_ + grp) * T_ * D_;
    const int NKT = T_ / 64;

    {   // prologue: stage kt=0
        const u32 base = sb + AQB;
#pragma unroll
        for (int i = 0; i < 2; i++) {
            const int id = t + i * 256, row = id >> 3, cq = id & 7;
            const u32 d = base + (u32)(row * 144 + cq * 16);
            const size_t go = kvbase + (size_t)row * 64 + cq * 8;
            cpasync16(d,         g_kh + go); cpasync16(d + 9216,  g_kl + go);
            cpasync16(d + 18432, g_vh + go); cpasync16(d + 27648, g_vl + go);
        }
        cpcommit();
    }

    for (int kt = 0; kt < NKT; kt++) {
        if (kt + 1 < NKT) {
            const size_t kb = kvbase + (size_t)(kt + 1) * 64 * D_;
            const u32 base = sb + AQB + (u32)((kt + 1) & 1) * AKVST;
#pragma unroll
            for (int i = 0; i < 2; i++) {
                const int id = t + i * 256, row = id >> 3, cq = id & 7;
                const u32 d = base + (u32)(row * 144 + cq * 16);
                const size_t go = kb + (size_t)row * 64 + cq * 8;
                cpasync16(d,         g_kh + go); cpasync16(d + 9216,  g_kl + go);
                cpasync16(d + 18432, g_vh + go); cpasync16(d + 27648, g_vl + go);
            }
            cpcommit();
            cpwait1();
        } else {
            cpwait0();
        }
        __syncthreads();

        const char* stb = smc + AQB + (size_t)(kt & 1) * AKVST;
        const u32* KhW = (const u32*)(stb);
        const u32* KlW = (const u32*)(stb + 9216);
        const __half* Vh = (const __half*)(stb + 18432);
        const __half* Vl = (const __half*)(stb + 27648);

        // ---- S = Qh (Kh + Kl)^T ----
        float sacc[8][4];
#pragma unroll
        for (int nt = 0; nt < 8; nt++)
#pragma unroll
            for (int i = 0; i < 4; i++) sacc[nt][i] = 0.0f;

        const int qw = (w * 16 + g) * ASW + tq;
#pragma unroll
        for (int c = 0; c < 4; c++) {
            const int qo = qw + c * 8;
            const u32 ah0 = QhW[qo],     ah1 = QhW[qo + 8 * ASW];
            const u32 ah2 = QhW[qo + 4], ah3 = QhW[qo + 8 * ASW + 4];
#pragma unroll
            for (int nt = 0; nt < 8; nt++) {
                const int ko = (nt * 8 + g) * ASW + tq + c * 8;
                mma16816(sacc[nt], ah0, ah1, ah2, ah3, KhW[ko], KhW[ko + 4]);
                mma16816(sacc[nt], ah0, ah1, ah2, ah3, KlW[ko], KlW[ko + 4]);
            }
        }

        // ---- online softmax ----
#pragma unroll
        for (int r = 0; r < 2; r++) {
            float rmax = -1e30f;
#pragma unroll
            for (int nt = 0; nt < 8; nt++)
                rmax = fmaxf(rmax, fmaxf(sacc[nt][2 * r], sacc[nt][2 * r + 1]));
            rmax = fmaxf(rmax, __shfl_xor_sync(0xffffffffu, rmax, 1));
            rmax = fmaxf(rmax, __shfl_xor_sync(0xffffffffu, rmax, 2));
            const float mn = fmaxf(mrow[r], rmax);
            const float corr = __expf(mrow[r] - mn);
            mrow[r] = mn;
            float rs = 0.0f;
#pragma unroll
            for (int nt = 0; nt < 8; nt++) {
                const float p0 = __expf(sacc[nt][2 * r] - mn);
                const float p1 = __expf(sacc[nt][2 * r + 1] - mn);
                sacc[nt][2 * r] = p0; sacc[nt][2 * r + 1] = p1;
                rs += p0 + p1;
            }
            rs += __shfl_xor_sync(0xffffffffu, rs, 1);
            rs += __shfl_xor_sync(0xffffffffu, rs, 2);
            lrow[r] = lrow[r] * corr + rs;
#pragma unroll
            for (int dt = 0; dt < 8; dt++) {
                oacc[dt][2 * r] *= corr; oacc[dt][2 * r + 1] *= corr;
            }
        }

        // ---- O += Ph (Vh + Vl) ----
        const int vrow = lane & 15;
        const int vcol = (lane >> 4) << 3;
#pragma unroll
        for (int c = 0; c < 4; c++) {
            u32 ph[4];
            ph[0] = packh(sacc[2 * c][0],     sacc[2 * c][1]);
            ph[1] = packh(sacc[2 * c][2],     sacc[2 * c][3]);
            ph[2] = packh(sacc[2 * c + 1][0], sacc[2 * c + 1][1]);
            ph[3] = packh(sacc[2 * c + 1][2], sacc[2 * c + 1][3]);
#pragma unroll
            for (int d2 = 0; d2 < 4; d2++) {
                u32 vh[4], vl[4];
                const int so = (c * 16 + vrow) * AS + d2 * 16 + vcol;
                ldsm4t(vh, &Vh[so]);
                ldsm4t(vl, &Vl[so]);
                mma16816(oacc[2 * d2],     ph[0], ph[1], ph[2], ph[3], vh[0], vh[1]);
                mma16816(oacc[2 * d2],     ph[0], ph[1], ph[2], ph[3], vl[0], vl[1]);
                mma16816(oacc[2 * d2 + 1], ph[0], ph[1], ph[2], ph[3], vh[2], vh[3]);
                mma16816(oacc[2 * d2 + 1], ph[0], ph[1], ph[2], ph[3], vl[2], vl[3]);
            }
        }
        __syncthreads();
    }

    // ---- normalize + write fp16 att (hi only; GEMM2 A operand) ----
    const float inv0 = 1.0f / lrow[0];
    const float inv1 = 1.0f / lrow[1];
    const size_t row0 = (size_t)b * T_ + (size_t)qt * 128 + w * 16 + g;
    const size_t row1 = row0 + 8;
#pragma unroll
    for (int dt = 0; dt < 8; dt++) {
        const int col = h * D_ + dt * 8 + 2 * tq;
        *(u32*)&g_ath[row0 * E_ + col] = packh(oacc[dt][0] * inv0, oacc[dt][1] * inv0);
        *(u32*)&g_ath[row1 * E_ + col] = packh(oacc[dt][2] * inv1, oacc[dt][3] * inv1);
    }
}

// ---------------------------------------------------------------------------
extern "C" void kernel_launch(void* const* d_in, const int* in_sizes, int n_in,
                              void* d_out, int out_size) {
    const float *x = 0, *cosp = 0, *sinp = 0, *attn_w = 0, *proj_w = 0;
    for (int i = 0; i < n_in; i++) {
        const float* p = (const float*)d_in[i];
        switch (in_sizes[i]) {
            case 8388608: x = p; break;
            case 6291456: attn_w = p; break;
            case 4194304: proj_w = p; break;
            case 65536:   if (!cosp) cosp = p; else sinp = p; break;
            default: break;
        }
    }
    float* out = (float*)d_out;

    float* qkv;
    __half *xh, *awh, *awl, *pwh, *pwl, *ath;
    cudaGetSymbolAddress((void**)&qkv, g_qkv);
    cudaGetSymbolAddress((void**)&xh,  g_xh);
    cudaGetSymbolAddress((void**)&awh, g_awh); cudaGetSymbolAddress((void**)&awl, g_awl);
    cudaGetSymbolAddress((void**)&pwh, g_pwh); cudaGetSymbolAddress((void**)&pwl, g_pwl);
    cudaGetSymbolAddress((void**)&ath, g_ath);

    // 0) fp32 -> fp16 (x: hi only; weights: hi+lo)
    split_hi_kernel<<<(8388608 / 4 + 255) / 256, 256>>>((const float4*)x, xh, 8388608 / 4);
    split2_kernel<<<(6291456 / 4 + 255) / 256, 256>>>((const float4*)attn_w, awh, awl, 6291456 / 4);
    split2_kernel<<<(4194304 / 4 + 255) / 256, 256>>>((const float4*)proj_w, pwh, pwl, 4194304 / 4);

    // 1) qkv = x @ attn_w^T   (M=4096, N=3072, K=2048)
    cudaFuncSetAttribute((const void*)gemm_f16_2t,
                         cudaFuncAttributeMaxDynamicSharedMemorySize, GEMM_SMEM);
    gemm_f16_2t<<<dim3(QKV_F / 256, (B_ * T_) / 128), 512, GEMM_SMEM>>>(
        xh, awh, awl, qkv, B_ * T_, QKV_F, E_);

    // 2) RoPE + GQA split -> fp16 q / k(h,l) / v(h,l)
    const size_t total = (size_t)B_ * T_ * QKV_F;
    rope_split_kernel<<<(unsigned)((total + 255) / 256), 256>>>(cosp, sinp);

    // 3) attention
    cudaFuncSetAttribute((const void*)attn_mma_kernel,
                         cudaFuncAttributeMaxDynamicSharedMemorySize, AT_SMEM_BYTES);
    attn_mma_kernel<<<dim3(T_ / 128, H_, B_), 256, AT_SMEM_BYTES>>>();

    // 4) out = att @ proj_w^T   (M=4096, N=2048, K=2048)
    gemm_f16_2t<<<dim3(E_ / 256, (B_ * T_) / 128), 512, GEMM_SMEM>>>(
        ath, pwh, pwl, out, B_ * T_, E_, E_);
}

// round 13
// speedup vs baseline: 5.3242x; 1.3362x over previous
#include <cuda_runtime.h>
#include <cuda_fp16.h>
#include <math.h>

#define B_    2
#define T_    2048
#define E_    2048
#define H_    32
#define G_    8
#define D_    64
#define QKV_F 3072
#define QPK_  4

typedef unsigned int u32;

// ---------------- scratch (device globals; no allocation allowed) ----------
__device__ float g_qkv[(size_t)B_ * T_ * QKV_F];
__device__ __half g_xh [(size_t)B_ * T_ * E_];
__device__ __half g_awh[(size_t)QKV_F * E_], g_awl[(size_t)QKV_F * E_];
__device__ __half g_pwh[(size_t)E_ * E_];
__device__ __half g_qh [(size_t)B_ * H_ * T_ * D_];
__device__ __half g_kh [(size_t)B_ * G_ * T_ * D_];
__device__ __half g_vh [(size_t)B_ * G_ * T_ * D_];
__device__ __half g_ath[(size_t)B_ * T_ * E_];

// ---------------- helpers --------------------------------------------------
__device__ __forceinline__ u32 packh(float lo, float hi) {
    u32 r;
    asm("cvt.rn.f16x2.f32 %0, %1, %2;" : "=r"(r) : "f"(hi), "f"(lo));
    return r;
}

__device__ __forceinline__ void mma16816(float* c, u32 a0, u32 a1, u32 a2, u32 a3,
                                         u32 b0, u32 b1) {
    asm volatile(
        "mma.sync.aligned.m16n8k16.row.col.f32.f16.f16.f32 "
        "{%0,%1,%2,%3}, {%4,%5,%6,%7}, {%8,%9}, {%0,%1,%2,%3};"
        : "+f"(c[0]), "+f"(c[1]), "+f"(c[2]), "+f"(c[3])
        : "r"(a0), "r"(a1), "r"(a2), "r"(a3), "r"(b0), "r"(b1));
}

__device__ __forceinline__ void ldsm4(u32* r, u32 a) {
    asm volatile("ldmatrix.sync.aligned.m8n8.x4.shared.b16 {%0,%1,%2,%3}, [%4];"
                 : "=r"(r[0]), "=r"(r[1]), "=r"(r[2]), "=r"(r[3]) : "r"(a));
}
__device__ __forceinline__ void ldsm4t(u32* r, const __half* p) {
    u32 a = (u32)__cvta_generic_to_shared(p);
    asm volatile("ldmatrix.sync.aligned.m8n8.x4.trans.shared.b16 {%0,%1,%2,%3}, [%4];"
                 : "=r"(r[0]), "=r"(r[1]), "=r"(r[2]), "=r"(r[3]) : "r"(a));
}

__device__ __forceinline__ u32 smem_u32(const void* p) {
    return (u32)__cvta_generic_to_shared(p);
}
__device__ __forceinline__ void cpasync16(u32 dst, const void* src) {
    asm volatile("cp.async.cg.shared.global [%0], [%1], 16;" :: "r"(dst), "l"(src));
}
__device__ __forceinline__ void cpcommit() { asm volatile("cp.async.commit_group;" ::: "memory"); }
__device__ __forceinline__ void cpwait0()  { asm volatile("cp.async.wait_group 0;" ::: "memory"); }
__device__ __forceinline__ void cpwait1()  { asm volatile("cp.async.wait_group 1;" ::: "memory"); }

// ---------------- split kernels --------------------------------------------
__global__ void split_hi_kernel(const float4* __restrict__ s, __half* __restrict__ h,
                                int n4) {
    int i = blockIdx.x * blockDim.x + threadIdx.x;
    if (i >= n4) return;
    float4 v = s[i];
    ((u32*)h)[2 * i]     = packh(v.x, v.y);
    ((u32*)h)[2 * i + 1] = packh(v.z, v.w);
}

__global__ void split2_kernel(const float4* __restrict__ s, __half* __restrict__ h,
                              __half* __restrict__ l, int n4) {
    int i = blockIdx.x * blockDim.x + threadIdx.x;
    if (i >= n4) return;
    float4 v = s[i];
    __half hx = __float2half_rn(v.x), hy = __float2half_rn(v.y);
    __half hz = __float2half_rn(v.z), hw = __float2half_rn(v.w);
    ((u32*)h)[2 * i]     = ((u32)__half_as_ushort(hy) << 16) | __half_as_ushort(hx);
    ((u32*)h)[2 * i + 1] = ((u32)__half_as_ushort(hw) << 16) | __half_as_ushort(hz);
    ((u32*)l)[2 * i]     = packh(v.x - __half2float(hx), v.y - __half2float(hy));
    ((u32*)l)[2 * i + 1] = packh(v.z - __half2float(hz), v.w - __half2float(hw));
}

// ===========================================================================
// GEMM1 (NT): C = Ah (Bh+Bl)^T, 2-term fp16 HMMA.
// 128x256 CTA tile, BK=64, 512 threads = 16 warps (4M x 4N), warp tile 32x64.
// ===========================================================================
#define GROW 144
#define GAST 18432
#define GBST 36864
#define GST2  (GAST + 2 * GBST)          // 92160
#define GEMM2T_SMEM (2 * GST2)           // 184320

__device__ __forceinline__ void stage_loads2(
    const __half* __restrict__ Ah,
    const __half* __restrict__ Bh, const __half* __restrict__ Bl,
    int K, int bm, int bn, int k0, u32 buf, int t) {
#pragma unroll
    for (int i = 0; i < 2; i++) {
        const int id = t + i * 512, row = id >> 3, cq = id & 7;
        const u32 d = buf + (u32)(row * GROW + cq * 16);
        cpasync16(d, Ah + (size_t)(bm + row) * K + k0 + cq * 8);
    }
#pragma unroll
    for (int i = 0; i < 4; i++) {
        const int id = t + i * 512, row = id >> 3, cq = id & 7;
        const u32 d = buf + GAST + (u32)(row * GROW + cq * 16);
        const size_t gb = (size_t)(bn + row) * K + k0 + cq * 8;
        cpasync16(d, Bh + gb); cpasync16(d + GBST, Bl + gb);
    }
}

__global__ __launch_bounds__(512, 1)
void gemm_f16_2t(const __half* __restrict__ Ah,
                 const __half* __restrict__ Bh, const __half* __restrict__ Bl,
                 float* __restrict__ C, int M, int N, int K) {
    extern __shared__ char smc[];
    const u32 sb = smem_u32(smc);

    const int t = threadIdx.x, lane = t & 31, w = t >> 5;
    const int g = lane >> 2, tq = lane & 3;
    const int wm = w & 3, wn = w >> 2;
    const int bm = blockIdx.y * 128, bn = blockIdx.x * 256;

    float acc[2][8][4];
#pragma unroll
    for (int mt = 0; mt < 2; mt++)
#pragma unroll
        for (int nt = 0; nt < 8; nt++)
#pragma unroll
            for (int i = 0; i < 4; i++) acc[mt][nt][i] = 0.0f;

    const int NS = K / 64;
    stage_loads2(Ah, Bh, Bl, K, bm, bn, 0, sb, t);
    cpcommit();

    const u32 arowl = (u32)(wm * 32 + (lane & 7) + ((lane >> 3) & 1) * 8);
    const u32 acoff = (u32)((lane >> 4) * 16);
    const u32 browl = (u32)(wn * 64 + (lane & 7) + ((lane >> 4) & 1) * 8);
    const u32 bcoff = (u32)(((lane >> 3) & 1) * 16);

    for (int s = 0; s < NS; s++) {
        if (s + 1 < NS) {
            stage_loads2(Ah, Bh, Bl, K, bm, bn, (s + 1) * 64,
                         sb + (u32)((s + 1) & 1) * GST2, t);
            cpcommit();
            cpwait1();
        } else {
            cpwait0();
        }
        __syncthreads();

        const u32 sbuf = sb + (u32)(s & 1) * GST2;
#pragma unroll
        for (int c = 0; c < 4; c++) {
            u32 ah[2][4], bh[8][2], bl[8][2];
#pragma unroll
            for (int mt = 0; mt < 2; mt++)
                ldsm4(ah[mt], sbuf + (arowl + mt * 16) * GROW + c * 32 + acoff);
#pragma unroll
            for (int p = 0; p < 4; p++) {
                const u32 a = sbuf + GAST + (browl + p * 16) * GROW + c * 32 + bcoff;
                u32 r[4];
                ldsm4(r, a);
                bh[2 * p][0] = r[0]; bh[2 * p][1] = r[1];
                bh[2 * p + 1][0] = r[2]; bh[2 * p + 1][1] = r[3];
                ldsm4(r, a + GBST);
                bl[2 * p][0] = r[0]; bl[2 * p][1] = r[1];
                bl[2 * p + 1][0] = r[2]; bl[2 * p + 1][1] = r[3];
            }
#pragma unroll
            for (int nt = 0; nt < 8; nt++)
#pragma unroll
                for (int mt = 0; mt < 2; mt++)
                    mma16816(acc[mt][nt], ah[mt][0], ah[mt][1], ah[mt][2], ah[mt][3],
                             bh[nt][0], bh[nt][1]);
#pragma unroll
            for (int nt = 0; nt < 8; nt++)
#pragma unroll
                for (int mt = 0; mt < 2; mt++)
                    mma16816(acc[mt][nt], ah[mt][0], ah[mt][1], ah[mt][2], ah[mt][3],
                             bl[nt][0], bl[nt][1]);
        }
        __syncthreads();
    }

#pragma unroll
    for (int mt = 0; mt < 2; mt++) {
        const int r0 = bm + wm * 32 + mt * 16 + g;
#pragma unroll
        for (int nt = 0; nt < 8; nt++) {
            const int cc = bn + wn * 64 + nt * 8 + 2 * tq;
            *(float2*)&C[(size_t)r0 * N + cc]       = make_float2(acc[mt][nt][0], acc[mt][nt][1]);
            *(float2*)&C[(size_t)(r0 + 8) * N + cc] = make_float2(acc[mt][nt][2], acc[mt][nt][3]);
        }
    }
}

// ===========================================================================
// GEMM2 (NT): C = Ah Bh^T, pure fp16 HMMA (same tiling, 1 term).
// Output fp32 to d_out. Stage: Ah 18432 + Bh 36864 = 55296 B, x2.
// ===========================================================================
#define GST1  (GAST + GBST)              // 55296
#define GEMM1T_SMEM (2 * GST1)           // 110592

__device__ __forceinline__ void stage_loads1(
    const __half* __restrict__ Ah, const __half* __restrict__ Bh,
    int K, int bm, int bn, int k0, u32 buf, int t) {
#pragma unroll
    for (int i = 0; i < 2; i++) {
        const int id = t + i * 512, row = id >> 3, cq = id & 7;
        const u32 d = buf + (u32)(row * GROW + cq * 16);
        cpasync16(d, Ah + (size_t)(bm + row) * K + k0 + cq * 8);
    }
#pragma unroll
    for (int i = 0; i < 4; i++) {
        const int id = t + i * 512, row = id >> 3, cq = id & 7;
        const u32 d = buf + GAST + (u32)(row * GROW + cq * 16);
        cpasync16(d, Bh + (size_t)(bn + row) * K + k0 + cq * 8);
    }
}

__global__ __launch_bounds__(512, 1)
void gemm_f16_1t(const __half* __restrict__ Ah, const __half* __restrict__ Bh,
                 float* __restrict__ C, int M, int N, int K) {
    extern __shared__ char smc[];
    const u32 sb = smem_u32(smc);

    const int t = threadIdx.x, lane = t & 31, w = t >> 5;
    const int g = lane >> 2, tq = lane & 3;
    const int wm = w & 3, wn = w >> 2;
    const int bm = blockIdx.y * 128, bn = blockIdx.x * 256;

    float acc[2][8][4];
#pragma unroll
    for (int mt = 0; mt < 2; mt++)
#pragma unroll
        for (int nt = 0; nt < 8; nt++)
#pragma unroll
            for (int i = 0; i < 4; i++) acc[mt][nt][i] = 0.0f;

    const int NS = K / 64;
    stage_loads1(Ah, Bh, K, bm, bn, 0, sb, t);
    cpcommit();

    const u32 arowl = (u32)(wm * 32 + (lane & 7) + ((lane >> 3) & 1) * 8);
    const u32 acoff = (u32)((lane >> 4) * 16);
    const u32 browl = (u32)(wn * 64 + (lane & 7) + ((lane >> 4) & 1) * 8);
    const u32 bcoff = (u32)(((lane >> 3) & 1) * 16);

    for (int s = 0; s < NS; s++) {
        if (s + 1 < NS) {
            stage_loads1(Ah, Bh, K, bm, bn, (s + 1) * 64,
                         sb + (u32)((s + 1) & 1) * GST1, t);
            cpcommit();
            cpwait1();
        } else {
            cpwait0();
        }
        __syncthreads();

        const u32 sbuf = sb + (u32)(s & 1) * GST1;
#pragma unroll
        for (int c = 0; c < 4; c++) {
            u32 ah[2][4], bh[8][2];
#pragma unroll
            for (int mt = 0; mt < 2; mt++)
                ldsm4(ah[mt], sbuf + (arowl + mt * 16) * GROW + c * 32 + acoff);
#pragma unroll
            for (int p = 0; p < 4; p++) {
                u32 r[4];
                ldsm4(r, sbuf + GAST + (browl + p * 16) * GROW + c * 32 + bcoff);
                bh[2 * p][0] = r[0]; bh[2 * p][1] = r[1];
                bh[2 * p + 1][0] = r[2]; bh[2 * p + 1][1] = r[3];
            }
#pragma unroll
            for (int nt = 0; nt < 8; nt++)
#pragma unroll
                for (int mt = 0; mt < 2; mt++)
                    mma16816(acc[mt][nt], ah[mt][0], ah[mt][1], ah[mt][2], ah[mt][3],
                             bh[nt][0], bh[nt][1]);
        }
        __syncthreads();
    }

#pragma unroll
    for (int mt = 0; mt < 2; mt++) {
        const int r0 = bm + wm * 32 + mt * 16 + g;
#pragma unroll
        for (int nt = 0; nt < 8; nt++) {
            const int cc = bn + wn * 64 + nt * 8 + 2 * tq;
            *(float2*)&C[(size_t)r0 * N + cc]       = make_float2(acc[mt][nt][0], acc[mt][nt][1]);
            *(float2*)&C[(size_t)(r0 + 8) * N + cc] = make_float2(acc[mt][nt][2], acc[mt][nt][3]);
        }
    }
}

// ---------------- RoPE + GQA split -> fp16 (hi only everywhere) ------------
__global__ void rope_split_kernel(const float* __restrict__ cosp,
                                  const float* __restrict__ sinp) {
    size_t idx = (size_t)blockIdx.x * blockDim.x + threadIdx.x;
    const size_t total = (size_t)B_ * T_ * QKV_F;
    if (idx >= total) return;

    const int d = (int)(idx & 63);
    const int f = (int)(idx % QKV_F);
    const size_t bt = idx / QKV_F;
    const int tpos = (int)(bt % T_);
    const int b = (int)(bt / T_);
    const int g = f / 384;
    const int slot = (f % 384) >> 6;

    float val = g_qkv[idx];
    if (slot <= 4) {
        const int dh = d & 31;
        const float c = cosp[tpos * 32 + dh];
        const float s = sinp[tpos * 32 + dh];
        const float other = g_qkv[idx ^ 32];
        val = (d < 32) ? (val * c - other * s) : fmaf(val, c, other * s);
    }

    if (slot < QPK_) {
        val *= 0.125f;
        const int h = g * QPK_ + slot;
        g_qh[(((size_t)b * H_ + h) * T_ + tpos) * D_ + d] = __float2half_rn(val);
    } else {
        const size_t o = (((size_t)b * G_ + g) * T_ + tpos) * D_ + d;
        if (slot == QPK_) g_kh[o] = __float2half_rn(val);
        else              g_vh[o] = __float2half_rn(val);
    }
}

// ===========================================================================
// Flash attention, pure fp16 HMMA: S = Qh Kh^T, O += Ph Vh.
// Block (b,h,128 q rows), 256 threads = 8 warps, kv tile 64, 2-stage cp.async.
// smem: Qh @0 (18432); stage st @18432 + st*18432: Kh+0, Vh+9216.
// ===========================================================================
#define AS  72
#define ASW 36
#define AQB   18432
#define AKVST 18432
#define AT_SMEM_BYTES (AQB + 2 * AKVST)     // 55296

__global__ __launch_bounds__(256, 2) void attn_mma_kernel() {
    extern __shared__ char smc[];
    const u32 sb = smem_u32(smc);
    __half* Qh = (__half*)smc;
    u32* QhW = (u32*)Qh;

    const int t = threadIdx.x, lane = t & 31, w = t >> 5;
    const int g = lane >> 2, tq = lane & 3;
    const int qt = blockIdx.x, h = blockIdx.y, b = blockIdx.z, grp = h >> 2;

    {   // stage Q (128 x 64)
        const __half* Qg = g_qh + (((size_t)b * H_ + h) * T_ + (size_t)qt * 128) * D_;
#pragma unroll
        for (int i = 0; i < 4; i++) {
            const int e = t + i * 256, row = e >> 3, c8 = (e & 7) * 8;
            *(uint4*)&Qh[row * AS + c8] = *(const uint4*)&Qg[row * D_ + c8];
        }
    }

    float oacc[8][4];
#pragma unroll
    for (int dt = 0; dt < 8; dt++)
#pragma unroll
        for (int i = 0; i < 4; i++) oacc[dt][i] = 0.0f;
    float mrow[2] = {-1e30f, -1e30f};
    float lrow[2] = {0.0f, 0.0f};

    const size_t kvbase = ((size_t)b * G_ + grp) * T_ * D_;
    const int NKT = T_ / 64;

    {   // prologue: stage kt=0 (Kh+Vh; 256 thr x 2 iters covers both tiles)
        const u32 base = sb + AQB;
#pragma unroll
        for (int i = 0; i < 2; i++) {
            const int id = t + i * 256, row = id >> 3, cq = id & 7;
            const u32 d = base + (u32)(row * 144 + cq * 16);
            const size_t go = kvbase + (size_t)row * 64 + cq * 8;
            cpasync16(d, g_kh + go); cpasync16(d + 9216, g_vh + go);
        }
        cpcommit();
    }

    for (int kt = 0; kt < NKT; kt++) {
        if (kt + 1 < NKT) {
            const size_t kb = kvbase + (size_t)(kt + 1) * 64 * D_;
            const u32 base = sb + AQB + (u32)((kt + 1) & 1) * AKVST;
#pragma unroll
            for (int i = 0; i < 2; i++) {
                const int id = t + i * 256, row = id >> 3, cq = id & 7;
                const u32 d = base + (u32)(row * 144 + cq * 16);
                const size_t go = kb + (size_t)row * 64 + cq * 8;
                cpasync16(d, g_kh + go); cpasync16(d + 9216, g_vh + go);
            }
            cpcommit();
            cpwait1();
        } else {
            cpwait0();
        }
        __syncthreads();

        const char* stb = smc + AQB + (size_t)(kt & 1) * AKVST;
        const u32* KhW = (const u32*)(stb);
        const __half* Vh = (const __half*)(stb + 9216);

        // ---- S = Qh Kh^T ----
        float sacc[8][4];
#pragma unroll
        for (int nt = 0; nt < 8; nt++)
#pragma unroll
            for (int i = 0; i < 4; i++) sacc[nt][i] = 0.0f;

        const int qw = (w * 16 + g) * ASW + tq;
#pragma unroll
        for (int c = 0; c < 4; c++) {
            const int qo = qw + c * 8;
            const u32 ah0 = QhW[qo],     ah1 = QhW[qo + 8 * ASW];
            const u32 ah2 = QhW[qo + 4], ah3 = QhW[qo + 8 * ASW + 4];
#pragma unroll
            for (int nt = 0; nt < 8; nt++) {
                const int ko = (nt * 8 + g) * ASW + tq + c * 8;
                mma16816(sacc[nt], ah0, ah1, ah2, ah3, KhW[ko], KhW[ko + 4]);
            }
        }

        // ---- online softmax ----
#pragma unroll
        for (int r = 0; r < 2; r++) {
            float rmax = -1e30f;
#pragma unroll
            for (int nt = 0; nt < 8; nt++)
                rmax = fmaxf(rmax, fmaxf(sacc[nt][2 * r], sacc[nt][2 * r + 1]));
            rmax = fmaxf(rmax, __shfl_xor_sync(0xffffffffu, rmax, 1));
            rmax = fmaxf(rmax, __shfl_xor_sync(0xffffffffu, rmax, 2));
            const float mn = fmaxf(mrow[r], rmax);
            const float corr = __expf(mrow[r] - mn);
            mrow[r] = mn;
            float rs = 0.0f;
#pragma unroll
            for (int nt = 0; nt < 8; nt++) {
                const float p0 = __expf(sacc[nt][2 * r] - mn);
                const float p1 = __expf(sacc[nt][2 * r + 1] - mn);
                sacc[nt][2 * r] = p0; sacc[nt][2 * r + 1] = p1;
                rs += p0 + p1;
            }
            rs += __shfl_xor_sync(0xffffffffu, rs, 1);
            rs += __shfl_xor_sync(0xffffffffu, rs, 2);
            lrow[r] = lrow[r] * corr + rs;
#pragma unroll
            for (int dt = 0; dt < 8; dt++) {
                oacc[dt][2 * r] *= corr; oacc[dt][2 * r + 1] *= corr;
            }
        }

        // ---- O += Ph Vh ----
        const int vrow = lane & 15;
        const int vcol = (lane >> 4) << 3;
#pragma unroll
        for (int c = 0; c < 4; c++) {
            u32 ph[4];
            ph[0] = packh(sacc[2 * c][0],     sacc[2 * c][1]);
            ph[1] = packh(sacc[2 * c][2],     sacc[2 * c][3]);
            ph[2] = packh(sacc[2 * c + 1][0], sacc[2 * c + 1][1]);
            ph[3] = packh(sacc[2 * c + 1][2], sacc[2 * c + 1][3]);
#pragma unroll
            for (int d2 = 0; d2 < 4; d2++) {
                u32 vh[4];
                ldsm4t(vh, &Vh[(c * 16 + vrow) * AS + d2 * 16 + vcol]);
                mma16816(oacc[2 * d2],     ph[0], ph[1], ph[2], ph[3], vh[0], vh[1]);
                mma16816(oacc[2 * d2 + 1], ph[0], ph[1], ph[2], ph[3], vh[2], vh[3]);
            }
        }
        __syncthreads();
    }

    // ---- normalize + write fp16 att ----
    const float inv0 = 1.0f / lrow[0];
    const float inv1 = 1.0f / lrow[1];
    const size_t row0 = (size_t)b * T_ + (size_t)qt * 128 + w * 16 + g;
    const size_t row1 = row0 + 8;
#pragma unroll
    for (int dt = 0; dt < 8; dt++) {
        const int col = h * D_ + dt * 8 + 2 * tq;
        *(u32*)&g_ath[row0 * E_ + col] = packh(oacc[dt][0] * inv0, oacc[dt][1] * inv0);
        *(u32*)&g_ath[row1 * E_ + col] = packh(oacc[dt][2] * inv1, oacc[dt][3] * inv1);
    }
}

// ---------------------------------------------------------------------------
extern "C" void kernel_launch(void* const* d_in, const int* in_sizes, int n_in,
                              void* d_out, int out_size) {
    const float *x = 0, *cosp = 0, *sinp = 0, *attn_w = 0, *proj_w = 0;
    for (int i = 0; i < n_in; i++) {
        const float* p = (const float*)d_in[i];
        switch (in_sizes[i]) {
            case 8388608: x = p; break;
            case 6291456: attn_w = p; break;
            case 4194304: proj_w = p; break;
            case 65536:   if (!cosp) cosp = p; else sinp = p; break;
            default: break;
        }
    }
    float* out = (float*)d_out;

    float* qkv;
    __half *xh, *awh, *awl, *pwh, *ath;
    cudaGetSymbolAddress((void**)&qkv, g_qkv);
    cudaGetSymbolAddress((void**)&xh,  g_xh);
    cudaGetSymbolAddress((void**)&awh, g_awh); cudaGetSymbolAddress((void**)&awl, g_awl);
    cudaGetSymbolAddress((void**)&pwh, g_pwh);
    cudaGetSymbolAddress((void**)&ath, g_ath);

    // 0) fp32 -> fp16 (x, proj_w: hi only; attn_w: hi+lo)
    split_hi_kernel<<<(8388608 / 4 + 255) / 256, 256>>>((const float4*)x, xh, 8388608 / 4);
    split2_kernel<<<(6291456 / 4 + 255) / 256, 256>>>((const float4*)attn_w, awh, awl, 6291456 / 4);
    split_hi_kernel<<<(4194304 / 4 + 255) / 256, 256>>>((const float4*)proj_w, pwh, 4194304 / 4);

    // 1) qkv = x @ attn_w^T  (2-term)
    cudaFuncSetAttribute((const void*)gemm_f16_2t,
                         cudaFuncAttributeMaxDynamicSharedMemorySize, GEMM2T_SMEM);
    gemm_f16_2t<<<dim3(QKV_F / 256, (B_ * T_) / 128), 512, GEMM2T_SMEM>>>(
        xh, awh, awl, qkv, B_ * T_, QKV_F, E_);

    // 2) RoPE + GQA split -> fp16 q/k/v
    const size_t total = (size_t)B_ * T_ * QKV_F;
    rope_split_kernel<<<(unsigned)((total + 255) / 256), 256>>>(cosp, sinp);

    // 3) attention (pure fp16)
    cudaFuncSetAttribute((const void*)attn_mma_kernel,
                         cudaFuncAttributeMaxDynamicSharedMemorySize, AT_SMEM_BYTES);
    attn_mma_kernel<<<dim3(T_ / 128, H_, B_), 256, AT_SMEM_BYTES>>>();

    // 4) out = att @ proj_w^T  (1-term)
    cudaFuncSetAttribute((const void*)gemm_f16_1t,
                         cudaFuncAttributeMaxDynamicSharedMemorySize, GEMM1T_SMEM);
    gemm_f16_1t<<<dim3(E_ / 256, (B_ * T_) / 128), 512, GEMM1T_SMEM>>>(
        ath, pwh, out, B_ * T_, E_, E_);
}

// round 14
// speedup vs baseline: 6.6131x; 1.2421x over previous
#include <cuda_runtime.h>
#include <cuda_fp16.h>
#include <math.h>

#define B_    2
#define T_    2048
#define E_    2048
#define H_    32
#define G_    8
#define D_    64
#define QKV_F 3072
#define QPK_  4

typedef unsigned int u32;

// ---------------- scratch (device globals; no allocation allowed) ----------
__device__ float g_qkv[(size_t)B_ * T_ * QKV_F];
__device__ __half g_xh [(size_t)B_ * T_ * E_];
__device__ __half g_awh[(size_t)QKV_F * E_];
__device__ __half g_pwh[(size_t)E_ * E_];
__device__ __half g_qh [(size_t)B_ * H_ * T_ * D_];
__device__ __half g_kh [(size_t)B_ * G_ * T_ * D_];
__device__ __half g_vh [(size_t)B_ * G_ * T_ * D_];
__device__ __half g_ath[(size_t)B_ * T_ * E_];

// ---------------- helpers --------------------------------------------------
__device__ __forceinline__ u32 packh(float lo, float hi) {
    u32 r;
    asm("cvt.rn.f16x2.f32 %0, %1, %2;" : "=r"(r) : "f"(hi), "f"(lo));
    return r;
}

__device__ __forceinline__ void mma16816(float* c, u32 a0, u32 a1, u32 a2, u32 a3,
                                         u32 b0, u32 b1) {
    asm volatile(
        "mma.sync.aligned.m16n8k16.row.col.f32.f16.f16.f32 "
        "{%0,%1,%2,%3}, {%4,%5,%6,%7}, {%8,%9}, {%0,%1,%2,%3};"
        : "+f"(c[0]), "+f"(c[1]), "+f"(c[2]), "+f"(c[3])
        : "r"(a0), "r"(a1), "r"(a2), "r"(a3), "r"(b0), "r"(b1));
}

__device__ __forceinline__ void ldsm4(u32* r, u32 a) {
    asm volatile("ldmatrix.sync.aligned.m8n8.x4.shared.b16 {%0,%1,%2,%3}, [%4];"
                 : "=r"(r[0]), "=r"(r[1]), "=r"(r[2]), "=r"(r[3]) : "r"(a));
}
__device__ __forceinline__ void ldsm4t(u32* r, const __half* p) {
    u32 a = (u32)__cvta_generic_to_shared(p);
    asm volatile("ldmatrix.sync.aligned.m8n8.x4.trans.shared.b16 {%0,%1,%2,%3}, [%4];"
                 : "=r"(r[0]), "=r"(r[1]), "=r"(r[2]), "=r"(r[3]) : "r"(a));
}

__device__ __forceinline__ u32 smem_u32(const void* p) {
    return (u32)__cvta_generic_to_shared(p);
}
__device__ __forceinline__ void cpasync16(u32 dst, const void* src) {
    asm volatile("cp.async.cg.shared.global [%0], [%1], 16;" :: "r"(dst), "l"(src));
}
__device__ __forceinline__ void cpcommit() { asm volatile("cp.async.commit_group;" ::: "memory"); }
__device__ __forceinline__ void cpwait0()  { asm volatile("cp.async.wait_group 0;" ::: "memory"); }
__device__ __forceinline__ void cpwait1()  { asm volatile("cp.async.wait_group 1;" ::: "memory"); }

// ---------------- split: fp32 -> fp16 (hi only) ----------------------------
__global__ void split_hi_kernel(const float4* __restrict__ s, __half* __restrict__ h,
                                int n4) {
    int i = blockIdx.x * blockDim.x + threadIdx.x;
    if (i >= n4) return;
    float4 v = s[i];
    ((u32*)h)[2 * i]     = packh(v.x, v.y);
    ((u32*)h)[2 * i + 1] = packh(v.z, v.w);
}

// ===========================================================================
// GEMM (NT): C = Ah Bh^T, pure fp16 HMMA, fp32 out.
// 128x256 CTA tile, BK=64, 512 threads = 16 warps (4M x 4N), warp tile 32x64.
// Stage: Ah 18432 + Bh 36864 = 55296 B, x2 stages.
// ===========================================================================
#define GROW 144
#define GAST 18432
#define GBST 36864
#define GST1  (GAST + GBST)              // 55296
#define GEMM1T_SMEM (2 * GST1)           // 110592

__device__ __forceinline__ void stage_loads1(
    const __half* __restrict__ Ah, const __half* __restrict__ Bh,
    int K, int bm, int bn, int k0, u32 buf, int t) {
#pragma unroll
    for (int i = 0; i < 2; i++) {
        const int id = t + i * 512, row = id >> 3, cq = id & 7;
        const u32 d = buf + (u32)(row * GROW + cq * 16);
        cpasync16(d, Ah + (size_t)(bm + row) * K + k0 + cq * 8);
    }
#pragma unroll
    for (int i = 0; i < 4; i++) {
        const int id = t + i * 512, row = id >> 3, cq = id & 7;
        const u32 d = buf + GAST + (u32)(row * GROW + cq * 16);
        cpasync16(d, Bh + (size_t)(bn + row) * K + k0 + cq * 8);
    }
}

__global__ __launch_bounds__(512, 1)
void gemm_f16_1t(const __half* __restrict__ Ah, const __half* __restrict__ Bh,
                 float* __restrict__ C, int M, int N, int K) {
    extern __shared__ char smc[];
    const u32 sb = smem_u32(smc);

    const int t = threadIdx.x, lane = t & 31, w = t >> 5;
    const int g = lane >> 2, tq = lane & 3;
    const int wm = w & 3, wn = w >> 2;
    const int bm = blockIdx.y * 128, bn = blockIdx.x * 256;

    float acc[2][8][4];
#pragma unroll
    for (int mt = 0; mt < 2; mt++)
#pragma unroll
        for (int nt = 0; nt < 8; nt++)
#pragma unroll
            for (int i = 0; i < 4; i++) acc[mt][nt][i] = 0.0f;

    const int NS = K / 64;
    stage_loads1(Ah, Bh, K, bm, bn, 0, sb, t);
    cpcommit();

    const u32 arowl = (u32)(wm * 32 + (lane & 7) + ((lane >> 3) & 1) * 8);
    const u32 acoff = (u32)((lane >> 4) * 16);
    const u32 browl = (u32)(wn * 64 + (lane & 7) + ((lane >> 4) & 1) * 8);
    const u32 bcoff = (u32)(((lane >> 3) & 1) * 16);

    for (int s = 0; s < NS; s++) {
        if (s + 1 < NS) {
            stage_loads1(Ah, Bh, K, bm, bn, (s + 1) * 64,
                         sb + (u32)((s + 1) & 1) * GST1, t);
            cpcommit();
            cpwait1();
        } else {
            cpwait0();
        }
        __syncthreads();

        const u32 sbuf = sb + (u32)(s & 1) * GST1;
#pragma unroll
        for (int c = 0; c < 4; c++) {
            u32 ah[2][4], bh[8][2];
#pragma unroll
            for (int mt = 0; mt < 2; mt++)
                ldsm4(ah[mt], sbuf + (arowl + mt * 16) * GROW + c * 32 + acoff);
#pragma unroll
            for (int p = 0; p < 4; p++) {
                u32 r[4];
                ldsm4(r, sbuf + GAST + (browl + p * 16) * GROW + c * 32 + bcoff);
                bh[2 * p][0] = r[0]; bh[2 * p][1] = r[1];
                bh[2 * p + 1][0] = r[2]; bh[2 * p + 1][1] = r[3];
            }
#pragma unroll
            for (int nt = 0; nt < 8; nt++)
#pragma unroll
                for (int mt = 0; mt < 2; mt++)
                    mma16816(acc[mt][nt], ah[mt][0], ah[mt][1], ah[mt][2], ah[mt][3],
                             bh[nt][0], bh[nt][1]);
        }
        __syncthreads();
    }

#pragma unroll
    for (int mt = 0; mt < 2; mt++) {
        const int r0 = bm + wm * 32 + mt * 16 + g;
#pragma unroll
        for (int nt = 0; nt < 8; nt++) {
            const int cc = bn + wn * 64 + nt * 8 + 2 * tq;
            *(float2*)&C[(size_t)r0 * N + cc]       = make_float2(acc[mt][nt][0], acc[mt][nt][1]);
            *(float2*)&C[(size_t)(r0 + 8) * N + cc] = make_float2(acc[mt][nt][2], acc[mt][nt][3]);
        }
    }
}

// ---------------- RoPE + GQA split -> fp16 ---------------------------------
__global__ void rope_split_kernel(const float* __restrict__ cosp,
                                  const float* __restrict__ sinp) {
    size_t idx = (size_t)blockIdx.x * blockDim.x + threadIdx.x;
    const size_t total = (size_t)B_ * T_ * QKV_F;
    if (idx >= total) return;

    const int d = (int)(idx & 63);
    const int f = (int)(idx % QKV_F);
    const size_t bt = idx / QKV_F;
    const int tpos = (int)(bt % T_);
    const int b = (int)(bt / T_);
    const int g = f / 384;
    const int slot = (f % 384) >> 6;

    float val = g_qkv[idx];
    if (slot <= 4) {
        const int dh = d & 31;
        const float c = cosp[tpos * 32 + dh];
        const float s = sinp[tpos * 32 + dh];
        const float other = g_qkv[idx ^ 32];
        val = (d < 32) ? (val * c - other * s) : fmaf(val, c, other * s);
    }

    if (slot < QPK_) {
        val *= 0.125f;
        const int h = g * QPK_ + slot;
        g_qh[(((size_t)b * H_ + h) * T_ + tpos) * D_ + d] = __float2half_rn(val);
    } else {
        const size_t o = (((size_t)b * G_ + g) * T_ + tpos) * D_ + d;
        if (slot == QPK_) g_kh[o] = __float2half_rn(val);
        else              g_vh[o] = __float2half_rn(val);
    }
}

// ===========================================================================
// Flash attention, pure fp16 HMMA: S = Qh Kh^T, O += Ph Vh.
// Block (b,h,128 q rows), 256 threads = 8 warps, kv tile 64, 2-stage cp.async.
// smem: Qh @0 (18432); stage st @18432 + st*18432: Kh+0, Vh+9216.
// ===========================================================================
#define AS  72
#define ASW 36
#define AQB   18432
#define AKVST 18432
#define AT_SMEM_BYTES (AQB + 2 * AKVST)     // 55296

__global__ __launch_bounds__(256, 2) void attn_mma_kernel() {
    extern __shared__ char smc[];
    const u32 sb = smem_u32(smc);
    __half* Qh = (__half*)smc;
    u32* QhW = (u32*)Qh;

    const int t = threadIdx.x, lane = t & 31, w = t >> 5;
    const int g = lane >> 2, tq = lane & 3;
    const int qt = blockIdx.x, h = blockIdx.y, b = blockIdx.z, grp = h >> 2;

    {   // stage Q (128 x 64)
        const __half* Qg = g_qh + (((size_t)b * H_ + h) * T_ + (size_t)qt * 128) * D_;
#pragma unroll
        for (int i = 0; i < 4; i++) {
            const int e = t + i * 256, row = e >> 3, c8 = (e & 7) * 8;
            *(uint4*)&Qh[row * AS + c8] = *(const uint4*)&Qg[row * D_ + c8];
        }
    }

    float oacc[8][4];
#pragma unroll
    for (int dt = 0; dt < 8; dt++)
#pragma unroll
        for (int i = 0; i < 4; i++) oacc[dt][i] = 0.0f;
    float mrow[2] = {-1e30f, -1e30f};
    float lrow[2] = {0.0f, 0.0f};

    const size_t kvbase = ((size_t)b * G_ + grp) * T_ * D_;
    const int NKT = T_ / 64;

    {   // prologue: stage kt=0
        const u32 base = sb + AQB;
#pragma unroll
        for (int i = 0; i < 2; i++) {
            const int id = t + i * 256, row = id >> 3, cq = id & 7;
            const u32 d = base + (u32)(row * 144 + cq * 16);
            const size_t go = kvbase + (size_t)row * 64 + cq * 8;
            cpasync16(d, g_kh + go); cpasync16(d + 9216, g_vh + go);
        }
        cpcommit();
    }

    for (int kt = 0; kt < NKT; kt++) {
        if (kt + 1 < NKT) {
            const size_t kb = kvbase + (size_t)(kt + 1) * 64 * D_;
            const u32 base = sb + AQB + (u32)((kt + 1) & 1) * AKVST;
#pragma unroll
            for (int i = 0; i < 2; i++) {
                const int id = t + i * 256, row = id >> 3, cq = id & 7;
                const u32 d = base + (u32)(row * 144 + cq * 16);
                const size_t go = kb + (size_t)row * 64 + cq * 8;
                cpasync16(d, g_kh + go); cpasync16(d + 9216, g_vh + go);
            }
            cpcommit();
            cpwait1();
        } else {
            cpwait0();
        }
        __syncthreads();

        const char* stb = smc + AQB + (size_t)(kt & 1) * AKVST;
        const u32* KhW = (const u32*)(stb);
        const __half* Vh = (const __half*)(stb + 9216);

        // ---- S = Qh Kh^T ----
        float sacc[8][4];
#pragma unroll
        for (int nt = 0; nt < 8; nt++)
#pragma unroll
            for (int i = 0; i < 4; i++) sacc[nt][i] = 0.0f;

        const int qw = (w * 16 + g) * ASW + tq;
#pragma unroll
        for (int c = 0; c < 4; c++) {
            const int qo = qw + c * 8;
            const u32 ah0 = QhW[qo],     ah1 = QhW[qo + 8 * ASW];
            const u32 ah2 = QhW[qo + 4], ah3 = QhW[qo + 8 * ASW + 4];
#pragma unroll
            for (int nt = 0; nt < 8; nt++) {
                const int ko = (nt * 8 + g) * ASW + tq + c * 8;
                mma16816(sacc[nt], ah0, ah1, ah2, ah3, KhW[ko], KhW[ko + 4]);
            }
        }

        // ---- online softmax ----
#pragma unroll
        for (int r = 0; r < 2; r++) {
            float rmax = -1e30f;
#pragma unroll
            for (int nt = 0; nt < 8; nt++)
                rmax = fmaxf(rmax, fmaxf(sacc[nt][2 * r], sacc[nt][2 * r + 1]));
            rmax = fmaxf(rmax, __shfl_xor_sync(0xffffffffu, rmax, 1));
            rmax = fmaxf(rmax, __shfl_xor_sync(0xffffffffu, rmax, 2));
            const float mn = fmaxf(mrow[r], rmax);
            const float corr = __expf(mrow[r] - mn);
            mrow[r] = mn;
            float rs = 0.0f;
#pragma unroll
            for (int nt = 0; nt < 8; nt++) {
                const float p0 = __expf(sacc[nt][2 * r] - mn);
                const float p1 = __expf(sacc[nt][2 * r + 1] - mn);
                sacc[nt][2 * r] = p0; sacc[nt][2 * r + 1] = p1;
                rs += p0 + p1;
            }
            rs += __shfl_xor_sync(0xffffffffu, rs, 1);
            rs += __shfl_xor_sync(0xffffffffu, rs, 2);
            lrow[r] = lrow[r] * corr + rs;
#pragma unroll
            for (int dt = 0; dt < 8; dt++) {
                oacc[dt][2 * r] *= corr; oacc[dt][2 * r + 1] *= corr;
            }
        }

        // ---- O += Ph Vh ----
        const int vrow = lane & 15;
        const int vcol = (lane >> 4) << 3;
#pragma unroll
        for (int c = 0; c < 4; c++) {
            u32 ph[4];
            ph[0] = packh(sacc[2 * c][0],     sacc[2 * c][1]);
            ph[1] = packh(sacc[2 * c][2],     sacc[2 * c][3]);
            ph[2] = packh(sacc[2 * c + 1][0], sacc[2 * c + 1][1]);
            ph[3] = packh(sacc[2 * c + 1][2], sacc[2 * c + 1][3]);
#pragma unroll
            for (int d2 = 0; d2 < 4; d2++) {
                u32 vh[4];
                ldsm4t(vh, &Vh[(c * 16 + vrow) * AS + d2 * 16 + vcol]);
                mma16816(oacc[2 * d2],     ph[0], ph[1], ph[2], ph[3], vh[0], vh[1]);
                mma16816(oacc[2 * d2 + 1], ph[0], ph[1], ph[2], ph[3], vh[2], vh[3]);
            }
        }
        __syncthreads();
    }

    // ---- normalize + write fp16 att ----
    const float inv0 = 1.0f / lrow[0];
    const float inv1 = 1.0f / lrow[1];
    const size_t row0 = (size_t)b * T_ + (size_t)qt * 128 + w * 16 + g;
    const size_t row1 = row0 + 8;
#pragma unroll
    for (int dt = 0; dt < 8; dt++) {
        const int col = h * D_ + dt * 8 + 2 * tq;
        *(u32*)&g_ath[row0 * E_ + col] = packh(oacc[dt][0] * inv0, oacc[dt][1] * inv0);
        *(u32*)&g_ath[row1 * E_ + col] = packh(oacc[dt][2] * inv1, oacc[dt][3] * inv1);
    }
}

// ---------------------------------------------------------------------------
extern "C" void kernel_launch(void* const* d_in, const int* in_sizes, int n_in,
                              void* d_out, int out_size) {
    const float *x = 0, *cosp = 0, *sinp = 0, *attn_w = 0, *proj_w = 0;
    for (int i = 0; i < n_in; i++) {
        const float* p = (const float*)d_in[i];
        switch (in_sizes[i]) {
            case 8388608: x = p; break;
            case 6291456: attn_w = p; break;
            case 4194304: proj_w = p; break;
            case 65536:   if (!cosp) cosp = p; else sinp = p; break;
            default: break;
        }
    }
    float* out = (float*)d_out;

    float* qkv;
    __half *xh, *awh, *pwh, *ath;
    cudaGetSymbolAddress((void**)&qkv, g_qkv);
    cudaGetSymbolAddress((void**)&xh,  g_xh);
    cudaGetSymbolAddress((void**)&awh, g_awh);
    cudaGetSymbolAddress((void**)&pwh, g_pwh);
    cudaGetSymbolAddress((void**)&ath, g_ath);

    // 0) fp32 -> fp16 (all hi-only now)
    split_hi_kernel<<<(8388608 / 4 + 255) / 256, 256>>>((const float4*)x, xh, 8388608 / 4);
    split_hi_kernel<<<(6291456 / 4 + 255) / 256, 256>>>((const float4*)attn_w, awh, 6291456 / 4);
    split_hi_kernel<<<(4194304 / 4 + 255) / 256, 256>>>((const float4*)proj_w, pwh, 4194304 / 4);

    // 1) qkv = x @ attn_w^T  (pure fp16)
    cudaFuncSetAttribute((const void*)gemm_f16_1t,
                         cudaFuncAttributeMaxDynamicSharedMemorySize, GEMM1T_SMEM);
    gemm_f16_1t<<<dim3(QKV_F / 256, (B_ * T_) / 128), 512, GEMM1T_SMEM>>>(
        xh, awh, qkv, B_ * T_, QKV_F, E_);

    // 2) RoPE + GQA split -> fp16 q/k/v
    const size_t total = (size_t)B_ * T_ * QKV_F;
    rope_split_kernel<<<(unsigned)((total + 255) / 256), 256>>>(cosp, sinp);

    // 3) attention (pure fp16)
    cudaFuncSetAttribute((const void*)attn_mma_kernel,
                         cudaFuncAttributeMaxDynamicSharedMemorySize, AT_SMEM_BYTES);
    attn_mma_kernel<<<dim3(T_ / 128, H_, B_), 256, AT_SMEM_BYTES>>>();

    // 4) out = att @ proj_w^T  (pure fp16)
    gemm_f16_1t<<<dim3(E_ / 256, (B_ * T_) / 128), 512, GEMM1T_SMEM>>>(
        ath, pwh, out, B_ * T_, E_, E_);
}